// round 1
// baseline (speedup 1.0000x reference)
#include <cuda_runtime.h>
#include <math.h>

#define BATCH 4
#define SEQ 2048
#define DM 768
#define NH 12
#define DH 64
#define ROWS (BATCH*SEQ)

// Scratch (allocation-free): q/k/v in [b][h][s][d], z in [b*s][h*d]
__device__ float g_q[(size_t)BATCH*NH*SEQ*DH];
__device__ float g_k[(size_t)BATCH*NH*SEQ*DH];
__device__ float g_v[(size_t)BATCH*NH*SEQ*DH];
__device__ float g_z[(size_t)ROWS*DM];

// ---------------------------------------------------------------------------
// Kernel 1: fused QKV projection.
// grid = (ROWS/64, NH, 3) ; block = 256 (16x16 threads, 4x4 frag each)
// out[sel][b][h][s][d] = sum_m x[b,s,m] * W[h,m,d] + bias[h,d]
// ---------------------------------------------------------------------------
__global__ void qkv_kernel(const float* __restrict__ x,
                           const float* __restrict__ Wq, const float* __restrict__ Wk,
                           const float* __restrict__ Wv,
                           const float* __restrict__ bq, const float* __restrict__ bk,
                           const float* __restrict__ bv)
{
    const int sel = blockIdx.z;
    const float* W    = (sel == 0) ? Wq : ((sel == 1) ? Wk : Wv);
    const float* bias = (sel == 0) ? bq : ((sel == 1) ? bk : bv);
    float* out        = (sel == 0) ? g_q : ((sel == 1) ? g_k : g_v);

    const int h    = blockIdx.y;
    const int row0 = blockIdx.x * 64;

    __shared__ float Xs[64][17];
    __shared__ float Ws[16][65];

    const int tid = threadIdx.x;
    const int ty  = tid >> 4;
    const int tx  = tid & 15;

    float acc[4][4] = {};

    const float* Wh = W + (size_t)h * DM * DH;

    for (int m0 = 0; m0 < DM; m0 += 16) {
        for (int idx = tid; idx < 64 * 16; idx += 256) {
            int r = idx >> 4, kk = idx & 15;
            Xs[r][kk] = x[(size_t)(row0 + r) * DM + m0 + kk];
        }
        for (int idx = tid; idx < 16 * 64; idx += 256) {
            int kk = idx >> 6, c = idx & 63;
            Ws[kk][c] = Wh[(size_t)(m0 + kk) * DH + c];
        }
        __syncthreads();

        #pragma unroll
        for (int kk = 0; kk < 16; kk++) {
            float a[4], b2[4];
            #pragma unroll
            for (int i = 0; i < 4; i++) a[i] = Xs[ty * 4 + i][kk];
            #pragma unroll
            for (int j = 0; j < 4; j++) b2[j] = Ws[kk][tx * 4 + j];
            #pragma unroll
            for (int i = 0; i < 4; i++)
                #pragma unroll
                for (int j = 0; j < 4; j++)
                    acc[i][j] = fmaf(a[i], b2[j], acc[i][j]);
        }
        __syncthreads();
    }

    #pragma unroll
    for (int i = 0; i < 4; i++) {
        int gr = row0 + ty * 4 + i;
        int bb = gr / SEQ, s = gr % SEQ;
        size_t base = (((size_t)bb * NH + h) * SEQ + s) * DH;
        #pragma unroll
        for (int j = 0; j < 4; j++) {
            int c = tx * 4 + j;
            out[base + c] = acc[i][j] + bias[h * DH + c];
        }
    }
}

// ---------------------------------------------------------------------------
// Kernel 2: causal flash attention, fp32 SIMT, 64x64 tiles, online softmax.
// grid = (SEQ/64, NH, BATCH) ; block = 256 ; dynamic smem = 4*64*65*4 bytes
// Writes z into g_z as [b*s][h*64+d].
// ---------------------------------------------------------------------------
__global__ void flash_kernel()
{
    extern __shared__ float sm[];
    float (*Qs)[65] = (float(*)[65])(sm);
    float (*Ks)[65] = (float(*)[65])(sm + 1 * 64 * 65);
    float (*Vs)[65] = (float(*)[65])(sm + 2 * 64 * 65);
    float (*Ps)[65] = (float(*)[65])(sm + 3 * 64 * 65);
    __shared__ float scale_sh[64];
    __shared__ float l_sh[64];

    const int qt = blockIdx.x;
    const int h  = blockIdx.y;
    const int b  = blockIdx.z;

    const size_t hb = ((size_t)b * NH + h) * SEQ * DH;
    const float* qp = g_q + hb;
    const float* kp = g_k + hb;
    const float* vp = g_v + hb;

    const int tid = threadIdx.x;
    const int ty  = tid >> 4;
    const int tx  = tid & 15;
    const int q0  = qt * 64;

    for (int idx = tid; idx < 64 * 64; idx += 256) {
        int r = idx >> 6, c = idx & 63;
        Qs[r][c] = qp[(size_t)(q0 + r) * DH + c];
    }

    float acc[4][4] = {};
    float m_r = -INFINITY, l_r = 0.f;

    const int nk = qt + 1;  // causal: only tiles with k0 <= q0
    for (int kt = 0; kt < nk; kt++) {
        const int k0 = kt * 64;
        __syncthreads();  // prior P@V done before K/V/P overwrite
        for (int idx = tid; idx < 64 * 64; idx += 256) {
            int r = idx >> 6, c = idx & 63;
            Ks[r][c] = kp[(size_t)(k0 + r) * DH + c];
            Vs[r][c] = vp[(size_t)(k0 + r) * DH + c];
        }
        __syncthreads();

        // S = Q @ K^T (64x64x64)
        float sf[4][4] = {};
        #pragma unroll 16
        for (int kk = 0; kk < 64; kk++) {
            float a[4], b2[4];
            #pragma unroll
            for (int i = 0; i < 4; i++) a[i] = Qs[ty * 4 + i][kk];
            #pragma unroll
            for (int j = 0; j < 4; j++) b2[j] = Ks[tx * 4 + j][kk];
            #pragma unroll
            for (int i = 0; i < 4; i++)
                #pragma unroll
                for (int j = 0; j < 4; j++)
                    sf[i][j] = fmaf(a[i], b2[j], sf[i][j]);
        }

        const bool diag = (kt == qt);
        #pragma unroll
        for (int i = 0; i < 4; i++)
            #pragma unroll
            for (int j = 0; j < 4; j++) {
                float v = sf[i][j] * 0.125f;  // 1/sqrt(64)
                if (diag && (tx * 4 + j > ty * 4 + i)) v = -1e30f;
                Ps[ty * 4 + i][tx * 4 + j] = v;
            }
        __syncthreads();

        // online softmax per row (threads 0..63)
        if (tid < 64) {
            float tmax = -INFINITY;
            for (int c = 0; c < 64; c++) tmax = fmaxf(tmax, Ps[tid][c]);
            float m_new = fmaxf(m_r, tmax);
            float scale = (m_r == -INFINITY) ? 0.f : __expf(m_r - m_new);
            float lsum = 0.f;
            for (int c = 0; c < 64; c++) {
                float p = __expf(Ps[tid][c] - m_new);
                Ps[tid][c] = p;
                lsum += p;
            }
            l_r = l_r * scale + lsum;
            m_r = m_new;
            scale_sh[tid] = scale;
        }
        __syncthreads();

        #pragma unroll
        for (int i = 0; i < 4; i++) {
            float sc = scale_sh[ty * 4 + i];
            #pragma unroll
            for (int j = 0; j < 4; j++) acc[i][j] *= sc;
        }

        // O += P @ V (64x64x64)
        #pragma unroll 16
        for (int kk = 0; kk < 64; kk++) {
            float a[4], b2[4];
            #pragma unroll
            for (int i = 0; i < 4; i++) a[i] = Ps[ty * 4 + i][kk];
            #pragma unroll
            for (int j = 0; j < 4; j++) b2[j] = Vs[kk][tx * 4 + j];
            #pragma unroll
            for (int i = 0; i < 4; i++)
                #pragma unroll
                for (int j = 0; j < 4; j++)
                    acc[i][j] = fmaf(a[i], b2[j], acc[i][j]);
        }
    }

    if (tid < 64) l_sh[tid] = l_r;
    __syncthreads();

    #pragma unroll
    for (int i = 0; i < 4; i++) {
        float inv = 1.f / l_sh[ty * 4 + i];
        size_t orow = ((size_t)b * SEQ + q0 + ty * 4 + i) * DM + h * DH;
        #pragma unroll
        for (int j = 0; j < 4; j++)
            g_z[orow + tx * 4 + j] = acc[i][j] * inv;
    }
}

// ---------------------------------------------------------------------------
// Kernel 3: output projection. out[row][n] = sum_m z[row][m]*W_O[m][n] + b_O[n]
// W_O given as [h][d][m] == row-major [768][768] with row = h*64+d.
// grid = (DM/64, ROWS/64) ; block = 256
// ---------------------------------------------------------------------------
__global__ void oproj_kernel(const float* __restrict__ Wo,
                             const float* __restrict__ bo,
                             float* __restrict__ out)
{
    const int n0   = blockIdx.x * 64;
    const int row0 = blockIdx.y * 64;

    __shared__ float Xs[64][17];
    __shared__ float Ws[16][65];

    const int tid = threadIdx.x;
    const int ty  = tid >> 4;
    const int tx  = tid & 15;

    float acc[4][4] = {};

    for (int m0 = 0; m0 < DM; m0 += 16) {
        for (int idx = tid; idx < 64 * 16; idx += 256) {
            int r = idx >> 4, kk = idx & 15;
            Xs[r][kk] = g_z[(size_t)(row0 + r) * DM + m0 + kk];
        }
        for (int idx = tid; idx < 16 * 64; idx += 256) {
            int kk = idx >> 6, c = idx & 63;
            Ws[kk][c] = Wo[(size_t)(m0 + kk) * DM + n0 + c];
        }
        __syncthreads();

        #pragma unroll
        for (int kk = 0; kk < 16; kk++) {
            float a[4], b2[4];
            #pragma unroll
            for (int i = 0; i < 4; i++) a[i] = Xs[ty * 4 + i][kk];
            #pragma unroll
            for (int j = 0; j < 4; j++) b2[j] = Ws[kk][tx * 4 + j];
            #pragma unroll
            for (int i = 0; i < 4; i++)
                #pragma unroll
                for (int j = 0; j < 4; j++)
                    acc[i][j] = fmaf(a[i], b2[j], acc[i][j]);
        }
        __syncthreads();
    }

    #pragma unroll
    for (int i = 0; i < 4; i++) {
        size_t orow = (size_t)(row0 + ty * 4 + i) * DM;
        #pragma unroll
        for (int j = 0; j < 4; j++) {
            int c = n0 + tx * 4 + j;
            out[orow + c] = acc[i][j] + bo[c];
        }
    }
}

extern "C" void kernel_launch(void* const* d_in, const int* in_sizes, int n_in,
                              void* d_out, int out_size)
{
    const float* x  = (const float*)d_in[0];
    const float* Wq = (const float*)d_in[1];
    const float* Wk = (const float*)d_in[2];
    const float* Wv = (const float*)d_in[3];
    const float* Wo = (const float*)d_in[4];
    const float* bq = (const float*)d_in[5];
    const float* bk = (const float*)d_in[6];
    const float* bv = (const float*)d_in[7];
    const float* bo = (const float*)d_in[8];
    float* out = (float*)d_out;

    const int flash_smem = 4 * 64 * 65 * (int)sizeof(float);  // 66,560 B
    cudaFuncSetAttribute(flash_kernel,
                         cudaFuncAttributeMaxDynamicSharedMemorySize, flash_smem);

    qkv_kernel<<<dim3(ROWS / 64, NH, 3), 256>>>(x, Wq, Wk, Wv, bq, bk, bv);
    flash_kernel<<<dim3(SEQ / 64, NH, BATCH), 256, flash_smem>>>();
    oproj_kernel<<<dim3(DM / 64, ROWS / 64), 256>>>(Wo, bo, out);
}

// round 2
// speedup vs baseline: 4.2783x; 4.2783x over previous
#include <cuda_runtime.h>
#include <math.h>
#include <stdint.h>

#define BATCH 4
#define SEQ 2048
#define DM 768
#define NH 12
#define DH 64
#define ROWS (BATCH*SEQ)

// Scratch (allocation-free)
__device__ float g_q[(size_t)BATCH*NH*SEQ*DH];
__device__ float g_k[(size_t)BATCH*NH*SEQ*DH];
__device__ float g_v[(size_t)BATCH*NH*SEQ*DH];
__device__ float g_z[(size_t)ROWS*DM];

__device__ __forceinline__ uint32_t f2tf(float f) {
    uint32_t u;
    asm("cvt.rna.tf32.f32 %0, %1;" : "=r"(u) : "f"(f));
    return u;
}

__device__ __forceinline__ void mma8(float* d, const uint32_t* a, const uint32_t* b) {
    asm volatile(
        "mma.sync.aligned.m16n8k8.row.col.f32.tf32.tf32.f32 "
        "{%0,%1,%2,%3}, {%4,%5,%6,%7}, {%8,%9}, {%0,%1,%2,%3};\n"
        : "+f"(d[0]), "+f"(d[1]), "+f"(d[2]), "+f"(d[3])
        : "r"(a[0]), "r"(a[1]), "r"(a[2]), "r"(a[3]), "r"(b[0]), "r"(b[1]));
}

// ---------------------------------------------------------------------------
// GEMM mainloop: C[128 x 64] += A[128 x K] @ B[K x 64], tf32 tensor cores.
// 256 threads = 8 warps, warp grid 4(m) x 2(n), warp tile 32x32.
// A row-major (lda), B row-major (ldb), caller pre-offsets A to row0, B to col0.
// ---------------------------------------------------------------------------
__device__ __forceinline__ void gemm_mainloop(
    const float* __restrict__ A, int lda,
    const float* __restrict__ B, int ldb, int K,
    uint32_t (*As)[36], uint32_t (*Bs)[72], float acc[2][4][4])
{
    const int tid  = threadIdx.x;
    const int lane = tid & 31;
    const int wid  = tid >> 5;
    const int wm   = wid >> 1;
    const int wn   = wid & 1;
    const int lq   = lane >> 2;  // 0..7
    const int lr   = lane & 3;   // 0..3

    for (int k0 = 0; k0 < K; k0 += 32) {
        #pragma unroll
        for (int i = 0; i < 4; i++) {
            int fid = tid + i * 256;
            int r = fid >> 3, c4 = fid & 7;
            float4 v = *(const float4*)(A + (size_t)r * lda + k0 + c4 * 4);
            As[r][c4*4+0] = f2tf(v.x); As[r][c4*4+1] = f2tf(v.y);
            As[r][c4*4+2] = f2tf(v.z); As[r][c4*4+3] = f2tf(v.w);
        }
        #pragma unroll
        for (int i = 0; i < 2; i++) {
            int fid = tid + i * 256;
            int r = fid >> 4, c4 = fid & 15;
            float4 v = *(const float4*)(B + (size_t)(k0 + r) * ldb + c4 * 4);
            Bs[r][c4*4+0] = f2tf(v.x); Bs[r][c4*4+1] = f2tf(v.y);
            Bs[r][c4*4+2] = f2tf(v.z); Bs[r][c4*4+3] = f2tf(v.w);
        }
        __syncthreads();

        #pragma unroll
        for (int kc = 0; kc < 4; kc++) {
            uint32_t a[2][4], b[4][2];
            #pragma unroll
            for (int mt = 0; mt < 2; mt++) {
                int base = wm * 32 + mt * 16 + lq;
                a[mt][0] = As[base    ][kc*8 + lr];
                a[mt][1] = As[base + 8][kc*8 + lr];
                a[mt][2] = As[base    ][kc*8 + 4 + lr];
                a[mt][3] = As[base + 8][kc*8 + 4 + lr];
            }
            #pragma unroll
            for (int nt = 0; nt < 4; nt++) {
                int col = wn * 32 + nt * 8 + lq;
                b[nt][0] = Bs[kc*8 + lr    ][col];
                b[nt][1] = Bs[kc*8 + 4 + lr][col];
            }
            #pragma unroll
            for (int mt = 0; mt < 2; mt++)
                #pragma unroll
                for (int nt = 0; nt < 4; nt++)
                    mma8(acc[mt][nt], a[mt], b[nt]);
        }
        __syncthreads();
    }
}

// ---------------------------------------------------------------------------
// Kernel 1: fused QKV. grid=(ROWS/128, NH, 3), block=256
// ---------------------------------------------------------------------------
__global__ void __launch_bounds__(256) qkv_kernel(
    const float* __restrict__ x,
    const float* __restrict__ Wq, const float* __restrict__ Wk,
    const float* __restrict__ Wv,
    const float* __restrict__ bq, const float* __restrict__ bk,
    const float* __restrict__ bv)
{
    __shared__ uint32_t As[128][36];
    __shared__ uint32_t Bs[32][72];

    const int sel = blockIdx.z;
    const float* W    = (sel == 0) ? Wq : ((sel == 1) ? Wk : Wv);
    const float* bias = (sel == 0) ? bq : ((sel == 1) ? bk : bv);
    float* out        = (sel == 0) ? g_q : ((sel == 1) ? g_k : g_v);

    const int h    = blockIdx.y;
    const int row0 = blockIdx.x * 128;

    float acc[2][4][4] = {};
    gemm_mainloop(x + (size_t)row0 * DM, DM, W + (size_t)h * DM * DH, DH, DM, As, Bs, acc);

    const int tid = threadIdx.x, lane = tid & 31, wid = tid >> 5;
    const int wm = wid >> 1, wn = wid & 1, lq = lane >> 2, lr = lane & 3;

    #pragma unroll
    for (int mt = 0; mt < 2; mt++) {
        #pragma unroll
        for (int nt = 0; nt < 4; nt++) {
            int gr0 = row0 + wm * 32 + mt * 16 + lq;
            int col = wn * 32 + nt * 8 + 2 * lr;
            float bz0 = bias[h * DH + col], bz1 = bias[h * DH + col + 1];
            #pragma unroll
            for (int half = 0; half < 2; half++) {
                int gr = gr0 + half * 8;
                int bb = gr / SEQ, s = gr % SEQ;
                size_t base = (((size_t)bb * NH + h) * SEQ + s) * DH;
                out[base + col]     = acc[mt][nt][half*2+0] + bz0;
                out[base + col + 1] = acc[mt][nt][half*2+1] + bz1;
            }
        }
    }
}

// ---------------------------------------------------------------------------
// Kernel 3: output projection. grid=(ROWS/128, DM/64), block=256
// ---------------------------------------------------------------------------
__global__ void __launch_bounds__(256) oproj_kernel(
    const float* __restrict__ Wo, const float* __restrict__ bo,
    float* __restrict__ out)
{
    __shared__ uint32_t As[128][36];
    __shared__ uint32_t Bs[32][72];

    const int row0 = blockIdx.x * 128;
    const int n0   = blockIdx.y * 64;

    float acc[2][4][4] = {};
    gemm_mainloop(g_z + (size_t)row0 * DM, DM, Wo + n0, DM, DM, As, Bs, acc);

    const int tid = threadIdx.x, lane = tid & 31, wid = tid >> 5;
    const int wm = wid >> 1, wn = wid & 1, lq = lane >> 2, lr = lane & 3;

    #pragma unroll
    for (int mt = 0; mt < 2; mt++) {
        #pragma unroll
        for (int nt = 0; nt < 4; nt++) {
            int gr0 = row0 + wm * 32 + mt * 16 + lq;
            int col = n0 + wn * 32 + nt * 8 + 2 * lr;
            float bz0 = bo[col], bz1 = bo[col + 1];
            #pragma unroll
            for (int half = 0; half < 2; half++) {
                size_t orow = (size_t)(gr0 + half * 8) * DM;
                out[orow + col]     = acc[mt][nt][half*2+0] + bz0;
                out[orow + col + 1] = acc[mt][nt][half*2+1] + bz1;
            }
        }
    }
}

// ---------------------------------------------------------------------------
// Kernel 2: causal flash attention, tf32 tensor cores.
// grid=(SEQ/128, NH, BATCH), block=256 (8 warps x 16 q-rows), k-tile 64.
// ---------------------------------------------------------------------------
__global__ void __launch_bounds__(256) flash_kernel()
{
    extern __shared__ uint32_t dsm[];
    uint32_t (*Qs)[68] = (uint32_t(*)[68])dsm;            // 128 x 68
    uint32_t (*Ps)[68] = (uint32_t(*)[68])(dsm + 128*68); // 128 x 68
    uint32_t (*Ks)[68] = (uint32_t(*)[68])(dsm + 2*128*68);         // 64 x 68
    uint32_t (*Vs)[72] = (uint32_t(*)[72])(dsm + 2*128*68 + 64*68); // 64 x 72

    const int qt = (int)gridDim.x - 1 - (int)blockIdx.x;  // big diagonals first
    const int h  = blockIdx.y;
    const int b  = blockIdx.z;
    const int q0 = qt * 128;

    const size_t hb = ((size_t)b * NH + h) * SEQ * DH;
    const float* qp = g_q + hb;
    const float* kp = g_k + hb;
    const float* vp = g_v + hb;

    const int tid  = threadIdx.x;
    const int lane = tid & 31;
    const int wid  = tid >> 5;
    const int lq   = lane >> 2, lr = lane & 3;
    const int wbase = wid * 16;

    // Load Q tile (pre-scaled by 1/sqrt(dh) = 0.125, exact power of 2)
    #pragma unroll
    for (int i = 0; i < 8; i++) {
        int fid = tid + i * 256;
        int r = fid >> 4, c4 = fid & 15;
        float4 v = *(const float4*)(qp + (size_t)(q0 + r) * DH + c4 * 4);
        Qs[r][c4*4+0] = f2tf(v.x * 0.125f); Qs[r][c4*4+1] = f2tf(v.y * 0.125f);
        Qs[r][c4*4+2] = f2tf(v.z * 0.125f); Qs[r][c4*4+3] = f2tf(v.w * 0.125f);
    }

    float o[8][4] = {};
    float m0 = -INFINITY, m1 = -INFINITY, l0 = 0.f, l1 = 0.f;

    const int nkt = 2 * qt + 2;
    for (int kt = 0; kt < nkt; kt++) {
        const int k0 = kt * 64;
        __syncthreads();
        #pragma unroll
        for (int i = 0; i < 4; i++) {
            int fid = tid + i * 256;
            int r = fid >> 4, c4 = fid & 15;
            float4 kv = *(const float4*)(kp + (size_t)(k0 + r) * DH + c4 * 4);
            float4 vv = *(const float4*)(vp + (size_t)(k0 + r) * DH + c4 * 4);
            Ks[r][c4*4+0] = f2tf(kv.x); Ks[r][c4*4+1] = f2tf(kv.y);
            Ks[r][c4*4+2] = f2tf(kv.z); Ks[r][c4*4+3] = f2tf(kv.w);
            Vs[r][c4*4+0] = f2tf(vv.x); Vs[r][c4*4+1] = f2tf(vv.y);
            Vs[r][c4*4+2] = f2tf(vv.z); Vs[r][c4*4+3] = f2tf(vv.w);
        }
        __syncthreads();

        // S = Q @ K^T : warp computes 16(q) x 64(k)
        float sf[8][4] = {};
        #pragma unroll
        for (int kc = 0; kc < 8; kc++) {
            uint32_t a[4];
            a[0] = Qs[wbase + lq    ][kc*8 + lr];
            a[1] = Qs[wbase + lq + 8][kc*8 + lr];
            a[2] = Qs[wbase + lq    ][kc*8 + 4 + lr];
            a[3] = Qs[wbase + lq + 8][kc*8 + 4 + lr];
            #pragma unroll
            for (int nt = 0; nt < 8; nt++) {
                uint32_t bb2[2];
                bb2[0] = Ks[nt*8 + lq][kc*8 + lr];
                bb2[1] = Ks[nt*8 + lq][kc*8 + 4 + lr];
                mma8(sf[nt], a, bb2);
            }
        }

        // Causal mask (only the last two k-tiles can touch the diagonal)
        if (kt >= 2 * qt) {
            const int grow0 = q0 + wbase + lq;
            #pragma unroll
            for (int nt = 0; nt < 8; nt++) {
                int gc = k0 + nt * 8 + 2 * lr;
                if (gc     > grow0)     sf[nt][0] = -1e30f;
                if (gc + 1 > grow0)     sf[nt][1] = -1e30f;
                if (gc     > grow0 + 8) sf[nt][2] = -1e30f;
                if (gc + 1 > grow0 + 8) sf[nt][3] = -1e30f;
            }
        }

        // Online softmax: rows r0 = lq, r1 = lq+8 (per-quad)
        float t0 = -INFINITY, t1 = -INFINITY;
        #pragma unroll
        for (int nt = 0; nt < 8; nt++) {
            t0 = fmaxf(t0, fmaxf(sf[nt][0], sf[nt][1]));
            t1 = fmaxf(t1, fmaxf(sf[nt][2], sf[nt][3]));
        }
        t0 = fmaxf(t0, __shfl_xor_sync(0xffffffffu, t0, 1));
        t0 = fmaxf(t0, __shfl_xor_sync(0xffffffffu, t0, 2));
        t1 = fmaxf(t1, __shfl_xor_sync(0xffffffffu, t1, 1));
        t1 = fmaxf(t1, __shfl_xor_sync(0xffffffffu, t1, 2));

        float mn0 = fmaxf(m0, t0), mn1 = fmaxf(m1, t1);
        float sc0 = __expf(m0 - mn0), sc1 = __expf(m1 - mn1);
        m0 = mn0; m1 = mn1;

        float s0 = 0.f, s1 = 0.f;
        #pragma unroll
        for (int nt = 0; nt < 8; nt++) {
            float p0 = __expf(sf[nt][0] - mn0);
            float p1 = __expf(sf[nt][1] - mn0);
            float p2 = __expf(sf[nt][2] - mn1);
            float p3 = __expf(sf[nt][3] - mn1);
            s0 += p0 + p1; s1 += p2 + p3;
            int col = nt * 8 + 2 * lr;
            Ps[wbase + lq    ][col]     = f2tf(p0);
            Ps[wbase + lq    ][col + 1] = f2tf(p1);
            Ps[wbase + lq + 8][col]     = f2tf(p2);
            Ps[wbase + lq + 8][col + 1] = f2tf(p3);
        }
        s0 += __shfl_xor_sync(0xffffffffu, s0, 1);
        s0 += __shfl_xor_sync(0xffffffffu, s0, 2);
        s1 += __shfl_xor_sync(0xffffffffu, s1, 1);
        s1 += __shfl_xor_sync(0xffffffffu, s1, 2);
        l0 = l0 * sc0 + s0;
        l1 = l1 * sc1 + s1;

        #pragma unroll
        for (int nt = 0; nt < 8; nt++) {
            o[nt][0] *= sc0; o[nt][1] *= sc0;
            o[nt][2] *= sc1; o[nt][3] *= sc1;
        }
        __syncwarp();

        // O += P @ V : 16(q) x 64(dh), k-dim = 64 keys
        #pragma unroll
        for (int kc = 0; kc < 8; kc++) {
            uint32_t a[4];
            a[0] = Ps[wbase + lq    ][kc*8 + lr];
            a[1] = Ps[wbase + lq + 8][kc*8 + lr];
            a[2] = Ps[wbase + lq    ][kc*8 + 4 + lr];
            a[3] = Ps[wbase + lq + 8][kc*8 + 4 + lr];
            #pragma unroll
            for (int nt = 0; nt < 8; nt++) {
                uint32_t bb2[2];
                bb2[0] = Vs[kc*8 + lr    ][nt*8 + lq];
                bb2[1] = Vs[kc*8 + 4 + lr][nt*8 + lq];
                mma8(o[nt], a, bb2);
            }
        }
        __syncwarp();
    }

    const float inv0 = 1.f / l0, inv1 = 1.f / l1;
    const size_t r0 = (size_t)b * SEQ + q0 + wbase + lq;
    #pragma unroll
    for (int nt = 0; nt < 8; nt++) {
        int col = h * DH + nt * 8 + 2 * lr;
        g_z[r0 * DM + col]           = o[nt][0] * inv0;
        g_z[r0 * DM + col + 1]       = o[nt][1] * inv0;
        g_z[(r0 + 8) * DM + col]     = o[nt][2] * inv1;
        g_z[(r0 + 8) * DM + col + 1] = o[nt][3] * inv1;
    }
}

extern "C" void kernel_launch(void* const* d_in, const int* in_sizes, int n_in,
                              void* d_out, int out_size)
{
    const float* x  = (const float*)d_in[0];
    const float* Wq = (const float*)d_in[1];
    const float* Wk = (const float*)d_in[2];
    const float* Wv = (const float*)d_in[3];
    const float* Wo = (const float*)d_in[4];
    const float* bq = (const float*)d_in[5];
    const float* bk = (const float*)d_in[6];
    const float* bv = (const float*)d_in[7];
    const float* bo = (const float*)d_in[8];
    float* out = (float*)d_out;

    const int flash_smem = (2*128*68 + 64*68 + 64*72) * (int)sizeof(uint32_t); // 105472
    cudaFuncSetAttribute(flash_kernel,
                         cudaFuncAttributeMaxDynamicSharedMemorySize, flash_smem);

    qkv_kernel<<<dim3(ROWS / 128, NH, 3), 256>>>(x, Wq, Wk, Wv, bq, bk, bv);
    flash_kernel<<<dim3(SEQ / 128, NH, BATCH), 256, flash_smem>>>();
    oproj_kernel<<<dim3(ROWS / 128, DM / 64), 256>>>(Wo, bo, out);
}

// round 4
// speedup vs baseline: 4.7414x; 1.1083x over previous
#include <cuda_runtime.h>
#include <math.h>
#include <stdint.h>

#define BATCH 4
#define SEQ 2048
#define DM 768
#define NH 12
#define DH 64
#define ROWS (BATCH*SEQ)

__device__ float g_q[(size_t)BATCH*NH*SEQ*DH];
__device__ float g_k[(size_t)BATCH*NH*SEQ*DH];
__device__ float g_v[(size_t)BATCH*NH*SEQ*DH];
__device__ float g_z[(size_t)ROWS*DM];

__device__ __forceinline__ uint32_t f2tf(float f) {
    uint32_t u;
    asm("cvt.rna.tf32.f32 %0, %1;" : "=r"(u) : "f"(f));
    return u;
}
__device__ __forceinline__ void mma8(float* d, const uint32_t* a, const uint32_t* b) {
    asm volatile(
        "mma.sync.aligned.m16n8k8.row.col.f32.tf32.tf32.f32 "
        "{%0,%1,%2,%3}, {%4,%5,%6,%7}, {%8,%9}, {%0,%1,%2,%3};\n"
        : "+f"(d[0]), "+f"(d[1]), "+f"(d[2]), "+f"(d[3])
        : "r"(a[0]), "r"(a[1]), "r"(a[2]), "r"(a[3]), "r"(b[0]), "r"(b[1]));
}
__device__ __forceinline__ uint32_t su32(const void* p) {
    return (uint32_t)__cvta_generic_to_shared(p);
}
#define CPA(dst, src) asm volatile("cp.async.cg.shared.global [%0], [%1], 16;" :: "r"(dst), "l"(src))
#define CPC() asm volatile("cp.async.commit_group;")
#define CPW1() asm volatile("cp.async.wait_group 1;")
#define CPW0() asm volatile("cp.async.wait_group 0;")

// ===========================================================================
// GEMM: C[128x128] = A[128xK] @ B[Kx128], block 128x128, 4 warps (64x64 each),
// BK=32, cp.async 2-stage. A pitch 36, B pitch 136 (conflict-free frag reads).
// ===========================================================================
#define AP 36
#define BP 136
#define A_ST (128*AP)
#define B_ST (32*BP)
#define GEMM_SMEM ((2*A_ST + 2*B_ST) * 4)

template <typename FB>
__device__ __forceinline__ void gemm128(const float* __restrict__ Ag, int lda,
                                        FB bsrc, int ntiles,
                                        float* As, float* Bs, float acc[4][8][4])
{
    const int tid = threadIdx.x;
    const int lane = tid & 31, wid = tid >> 5;
    const int wm = wid >> 1, wn = wid & 1;
    const int lq = lane >> 2, lr = lane & 3;

    auto load_tile = [&](int t, int s) {
        #pragma unroll
        for (int i = 0; i < 8; i++) {
            int idx = tid + i * 128;
            int r = idx >> 3, c4 = idx & 7;
            CPA(su32(&As[s*A_ST + r*AP + c4*4]), Ag + (size_t)r * lda + t*32 + c4*4);
        }
        #pragma unroll
        for (int i = 0; i < 8; i++) {
            int idx = tid + i * 128;
            int kr = idx >> 5, c4 = idx & 31;
            CPA(su32(&Bs[s*B_ST + kr*BP + c4*4]), bsrc(t*32 + kr, c4));
        }
    };

    load_tile(0, 0); CPC();

    for (int t = 0; t < ntiles; t++) {
        if (t + 1 < ntiles) { load_tile(t + 1, (t + 1) & 1); CPC(); CPW1(); }
        else { CPW0(); }
        __syncthreads();

        const float* A_ = As + (t & 1) * A_ST;
        const float* B_ = Bs + (t & 1) * B_ST;
        #pragma unroll
        for (int kc = 0; kc < 4; kc++) {
            uint32_t a[4][4], b[8][2];
            #pragma unroll
            for (int mt = 0; mt < 4; mt++) {
                int r0 = wm*64 + mt*16 + lq;
                a[mt][0] = f2tf(A_[r0*AP + kc*8 + lr]);
                a[mt][1] = f2tf(A_[(r0+8)*AP + kc*8 + lr]);
                a[mt][2] = f2tf(A_[r0*AP + kc*8 + 4 + lr]);
                a[mt][3] = f2tf(A_[(r0+8)*AP + kc*8 + 4 + lr]);
            }
            #pragma unroll
            for (int nt = 0; nt < 8; nt++) {
                int col = wn*64 + nt*8 + lq;
                b[nt][0] = f2tf(B_[(kc*8+lr)*BP + col]);
                b[nt][1] = f2tf(B_[(kc*8+4+lr)*BP + col]);
            }
            #pragma unroll
            for (int mt = 0; mt < 4; mt++)
                #pragma unroll
                for (int nt = 0; nt < 8; nt++)
                    mma8(acc[mt][nt], a[mt], b[nt]);
        }
        __syncthreads();
    }
}

// ---------------------------------------------------------------------------
// Kernel 1: fused QKV. grid=(ROWS/128, 18), block=128.
// blockIdx.y -> sel = y/6, heads h0=(y%6)*2 .. h0+1 (128 cols = 2 heads).
// ---------------------------------------------------------------------------
__global__ void __launch_bounds__(128) qkv_kernel(
    const float* __restrict__ x,
    const float* __restrict__ Wq, const float* __restrict__ Wk,
    const float* __restrict__ Wv,
    const float* __restrict__ bq, const float* __restrict__ bk,
    const float* __restrict__ bv)
{
    extern __shared__ float sm[];
    float* As = sm;
    float* Bs = sm + 2*A_ST;

    const int nb = blockIdx.y;
    const int sel = nb / 6;
    const int h0 = (nb % 6) * 2;
    const float* W    = (sel == 0) ? Wq : ((sel == 1) ? Wk : Wv);
    const float* bias = (sel == 0) ? bq : ((sel == 1) ? bk : bv);
    float* out        = (sel == 0) ? g_q : ((sel == 1) ? g_k : g_v);

    const int row0 = blockIdx.x * 128;

    float acc[4][8][4] = {};
    auto bsrc = [&](int k, int c4) {
        int head = h0 + (c4 >> 4);
        return W + (size_t)head * DM * DH + (size_t)k * DH + (c4 & 15) * 4;
    };
    gemm128(x + (size_t)row0 * DM, DM, bsrc, DM/32, As, Bs, acc);

    const int tid = threadIdx.x, lane = tid & 31, wid = tid >> 5;
    const int wm = wid >> 1, wn = wid & 1, lq = lane >> 2, lr = lane & 3;

    #pragma unroll
    for (int mt = 0; mt < 4; mt++) {
        #pragma unroll
        for (int nt = 0; nt < 8; nt++) {
            int c = wn*64 + nt*8 + 2*lr;
            int h = h0 + (c >> 6), d = c & 63;
            float bz0 = bias[h*DH + d], bz1 = bias[h*DH + d + 1];
            #pragma unroll
            for (int half = 0; half < 2; half++) {
                int gr = row0 + wm*64 + mt*16 + lq + half*8;
                int bb = gr / SEQ, s = gr % SEQ;
                size_t base = (((size_t)bb*NH + h)*SEQ + s)*DH + d;
                out[base]     = acc[mt][nt][half*2+0] + bz0;
                out[base + 1] = acc[mt][nt][half*2+1] + bz1;
            }
        }
    }
}

// ---------------------------------------------------------------------------
// Kernel 3: output projection. grid=(ROWS/128, 6), block=128.
// ---------------------------------------------------------------------------
__global__ void __launch_bounds__(128) oproj_kernel(
    const float* __restrict__ Wo, const float* __restrict__ bo,
    float* __restrict__ out)
{
    extern __shared__ float sm[];
    float* As = sm;
    float* Bs = sm + 2*A_ST;

    const int row0 = blockIdx.x * 128;
    const int n0   = blockIdx.y * 128;

    float acc[4][8][4] = {};
    auto bsrc = [&](int k, int c4) {
        return Wo + (size_t)k * DM + n0 + c4 * 4;
    };
    gemm128(g_z + (size_t)row0 * DM, DM, bsrc, DM/32, As, Bs, acc);

    const int tid = threadIdx.x, lane = tid & 31, wid = tid >> 5;
    const int wm = wid >> 1, wn = wid & 1, lq = lane >> 2, lr = lane & 3;

    #pragma unroll
    for (int mt = 0; mt < 4; mt++) {
        #pragma unroll
        for (int nt = 0; nt < 8; nt++) {
            int c = n0 + wn*64 + nt*8 + 2*lr;
            float bz0 = bo[c], bz1 = bo[c + 1];
            #pragma unroll
            for (int half = 0; half < 2; half++) {
                size_t orow = (size_t)(row0 + wm*64 + mt*16 + lq + half*8) * DM;
                out[orow + c]     = acc[mt][nt][half*2+0] + bz0;
                out[orow + c + 1] = acc[mt][nt][half*2+1] + bz1;
            }
        }
    }
}

// ===========================================================================
// Kernel 2: causal flash attention.
// grid=(SEQ/256, NH, BATCH), block=256 (8 warps x 32 q-rows), k-tile 64.
// Q[256x64] pitch 68, P pitch 68, K pitch 68 (x2 stages), V pitch 72 (x2).
// ===========================================================================
#define QTILE 256
#define QP 68
#define KP 68
#define VP 72
#define K_ST (64*KP)
#define V_ST (64*VP)
#define Q_OFF 0
#define P_OFF (QTILE*QP)
#define K_OFF (2*QTILE*QP)
#define V_OFF (K_OFF + 2*K_ST)
#define FLASH_SMEM ((2*QTILE*QP + 2*K_ST + 2*V_ST) * 4)

__global__ void __launch_bounds__(256) flash_kernel()
{
    extern __shared__ float sm[];
    float* Qs = sm + Q_OFF;
    float* Ps = sm + P_OFF;

    const int qt = (int)gridDim.x - 1 - (int)blockIdx.x;  // big diagonals first
    const int h  = blockIdx.y;
    const int b  = blockIdx.z;
    const int q0 = qt * QTILE;

    const size_t hb = ((size_t)b * NH + h) * SEQ * DH;
    const float* qp = g_q + hb;
    const float* kp = g_k + hb;
    const float* vp = g_v + hb;

    const int tid  = threadIdx.x;
    const int lane = tid & 31;
    const int wid  = tid >> 5;
    const int lq   = lane >> 2, lr = lane & 3;
    const int wbase = wid * 32;

    auto loadKV = [&](int kt, int s) {
        int k0 = kt * 64;
        #pragma unroll
        for (int i = 0; i < 4; i++) {
            int idx = tid + i * 256;
            int r = idx >> 4, c4 = idx & 15;
            CPA(su32(&sm[K_OFF + s*K_ST + r*KP + c4*4]), kp + (size_t)(k0+r)*DH + c4*4);
            CPA(su32(&sm[V_OFF + s*V_ST + r*VP + c4*4]), vp + (size_t)(k0+r)*DH + c4*4);
        }
    };

    // prologue: Q + KV tile 0 in group 0
    #pragma unroll
    for (int i = 0; i < 16; i++) {
        int idx = tid + i * 256;
        int r = idx >> 4, c4 = idx & 15;
        CPA(su32(&Qs[r*QP + c4*4]), qp + (size_t)(q0+r)*DH + c4*4);
    }
    loadKV(0, 0);
    CPC();

    float o[2][8][4] = {};
    float mrow[2][2], lrow[2][2];
    #pragma unroll
    for (int mt = 0; mt < 2; mt++) { mrow[mt][0]=-INFINITY; mrow[mt][1]=-INFINITY; lrow[mt][0]=0.f; lrow[mt][1]=0.f; }

    const int nkt = 4*qt + 4;
    for (int kt = 0; kt < nkt; kt++) {
        if (kt + 1 < nkt) { loadKV(kt + 1, (kt + 1) & 1); CPC(); CPW1(); }
        else { CPW0(); }
        __syncthreads();

        const int k0 = kt * 64;
        const float* K_ = sm + K_OFF + (kt & 1) * K_ST;
        const float* V_ = sm + V_OFF + (kt & 1) * V_ST;

        // S = Q @ K^T : warp tile 32(q) x 64(k)
        float sf[2][8][4] = {};
        #pragma unroll
        for (int kc = 0; kc < 8; kc++) {
            uint32_t a[2][4];
            #pragma unroll
            for (int mt = 0; mt < 2; mt++) {
                int r0 = wbase + mt*16 + lq;
                a[mt][0] = f2tf(Qs[r0*QP + kc*8 + lr]);
                a[mt][1] = f2tf(Qs[(r0+8)*QP + kc*8 + lr]);
                a[mt][2] = f2tf(Qs[r0*QP + kc*8 + 4 + lr]);
                a[mt][3] = f2tf(Qs[(r0+8)*QP + kc*8 + 4 + lr]);
            }
            #pragma unroll
            for (int nt = 0; nt < 8; nt++) {
                int key = nt*8 + lq;
                uint32_t bb2[2];
                bb2[0] = f2tf(K_[key*KP + kc*8 + lr]);
                bb2[1] = f2tf(K_[key*KP + kc*8 + 4 + lr]);
                mma8(sf[0][nt], a[0], bb2);
                mma8(sf[1][nt], a[1], bb2);
            }
        }

        // scale + causal mask
        const bool nm = (k0 + 63 > q0 + wbase);
        #pragma unroll
        for (int mt = 0; mt < 2; mt++) {
            int grow0 = q0 + wbase + mt*16 + lq;
            #pragma unroll
            for (int nt = 0; nt < 8; nt++) {
                #pragma unroll
                for (int e = 0; e < 4; e++) {
                    float v = sf[mt][nt][e] * 0.125f;
                    if (nm) {
                        int gc = k0 + nt*8 + 2*lr + (e & 1);
                        int grow = grow0 + ((e >= 2) ? 8 : 0);
                        if (gc > grow) v = -1e30f;
                    }
                    sf[mt][nt][e] = v;
                }
            }
        }

        // online softmax per mt (rows lq, lq+8 per quad)
        #pragma unroll
        for (int mt = 0; mt < 2; mt++) {
            float t0 = -INFINITY, t1 = -INFINITY;
            #pragma unroll
            for (int nt = 0; nt < 8; nt++) {
                t0 = fmaxf(t0, fmaxf(sf[mt][nt][0], sf[mt][nt][1]));
                t1 = fmaxf(t1, fmaxf(sf[mt][nt][2], sf[mt][nt][3]));
            }
            t0 = fmaxf(t0, __shfl_xor_sync(0xffffffffu, t0, 1));
            t0 = fmaxf(t0, __shfl_xor_sync(0xffffffffu, t0, 2));
            t1 = fmaxf(t1, __shfl_xor_sync(0xffffffffu, t1, 1));
            t1 = fmaxf(t1, __shfl_xor_sync(0xffffffffu, t1, 2));

            float mn0 = fmaxf(mrow[mt][0], t0), mn1 = fmaxf(mrow[mt][1], t1);
            float sc0 = __expf(mrow[mt][0] - mn0), sc1 = __expf(mrow[mt][1] - mn1);
            mrow[mt][0] = mn0; mrow[mt][1] = mn1;

            float s0 = 0.f, s1 = 0.f;
            int rA = wbase + mt*16 + lq;
            #pragma unroll
            for (int nt = 0; nt < 8; nt++) {
                float p0 = __expf(sf[mt][nt][0] - mn0);
                float p1 = __expf(sf[mt][nt][1] - mn0);
                float p2 = __expf(sf[mt][nt][2] - mn1);
                float p3 = __expf(sf[mt][nt][3] - mn1);
                s0 += p0 + p1; s1 += p2 + p3;
                int col = nt*8 + 2*lr;
                Ps[rA*QP + col]         = __uint_as_float(f2tf(p0));
                Ps[rA*QP + col + 1]     = __uint_as_float(f2tf(p1));
                Ps[(rA+8)*QP + col]     = __uint_as_float(f2tf(p2));
                Ps[(rA+8)*QP + col + 1] = __uint_as_float(f2tf(p3));
            }
            s0 += __shfl_xor_sync(0xffffffffu, s0, 1);
            s0 += __shfl_xor_sync(0xffffffffu, s0, 2);
            s1 += __shfl_xor_sync(0xffffffffu, s1, 1);
            s1 += __shfl_xor_sync(0xffffffffu, s1, 2);
            lrow[mt][0] = lrow[mt][0] * sc0 + s0;
            lrow[mt][1] = lrow[mt][1] * sc1 + s1;

            #pragma unroll
            for (int nt = 0; nt < 8; nt++) {
                o[mt][nt][0] *= sc0; o[mt][nt][1] *= sc0;
                o[mt][nt][2] *= sc1; o[mt][nt][3] *= sc1;
            }
        }
        __syncwarp();

        // O += P @ V : 32(q) x 64(dh) over 64 keys
        #pragma unroll
        for (int kc = 0; kc < 8; kc++) {
            uint32_t a[2][4];
            #pragma unroll
            for (int mt = 0; mt < 2; mt++) {
                int r0 = wbase + mt*16 + lq;
                a[mt][0] = __float_as_uint(Ps[r0*QP + kc*8 + lr]);
                a[mt][1] = __float_as_uint(Ps[(r0+8)*QP + kc*8 + lr]);
                a[mt][2] = __float_as_uint(Ps[r0*QP + kc*8 + 4 + lr]);
                a[mt][3] = __float_as_uint(Ps[(r0+8)*QP + kc*8 + 4 + lr]);
            }
            #pragma unroll
            for (int nt = 0; nt < 8; nt++) {
                uint32_t bb2[2];
                bb2[0] = f2tf(V_[(kc*8+lr)*VP + nt*8 + lq]);
                bb2[1] = f2tf(V_[(kc*8+4+lr)*VP + nt*8 + lq]);
                mma8(o[0][nt], a[0], bb2);
                mma8(o[1][nt], a[1], bb2);
            }
        }
        __syncwarp();
        __syncthreads();
    }

    #pragma unroll
    for (int mt = 0; mt < 2; mt++) {
        float inv0 = 1.f / lrow[mt][0], inv1 = 1.f / lrow[mt][1];
        size_t r0 = (size_t)b * SEQ + q0 + wbase + mt*16 + lq;
        #pragma unroll
        for (int nt = 0; nt < 8; nt++) {
            int col = h*DH + nt*8 + 2*lr;
            g_z[r0 * DM + col]           = o[mt][nt][0] * inv0;
            g_z[r0 * DM + col + 1]       = o[mt][nt][1] * inv0;
            g_z[(r0 + 8) * DM + col]     = o[mt][nt][2] * inv1;
            g_z[(r0 + 8) * DM + col + 1] = o[mt][nt][3] * inv1;
        }
    }
}

extern "C" void kernel_launch(void* const* d_in, const int* in_sizes, int n_in,
                              void* d_out, int out_size)
{
    const float* x  = (const float*)d_in[0];
    const float* Wq = (const float*)d_in[1];
    const float* Wk = (const float*)d_in[2];
    const float* Wv = (const float*)d_in[3];
    const float* Wo = (const float*)d_in[4];
    const float* bq = (const float*)d_in[5];
    const float* bk = (const float*)d_in[6];
    const float* bv = (const float*)d_in[7];
    const float* bo = (const float*)d_in[8];
    float* out = (float*)d_out;

    cudaFuncSetAttribute(qkv_kernel,  cudaFuncAttributeMaxDynamicSharedMemorySize, GEMM_SMEM);
    cudaFuncSetAttribute(oproj_kernel, cudaFuncAttributeMaxDynamicSharedMemorySize, GEMM_SMEM);
    cudaFuncSetAttribute(flash_kernel, cudaFuncAttributeMaxDynamicSharedMemorySize, FLASH_SMEM);

    qkv_kernel<<<dim3(ROWS / 128, 18), 128, GEMM_SMEM>>>(x, Wq, Wk, Wv, bq, bk, bv);
    flash_kernel<<<dim3(SEQ / QTILE, NH, BATCH), 256, FLASH_SMEM>>>();
    oproj_kernel<<<dim3(ROWS / 128, 6), 128, GEMM_SMEM>>>(Wo, bo, out);
}

// round 5
// speedup vs baseline: 5.0239x; 1.0596x over previous
#include <cuda_runtime.h>
#include <math.h>
#include <stdint.h>

#define BATCH 4
#define SEQ 2048
#define DM 768
#define NH 12
#define DH 64
#define ROWS (BATCH*SEQ)

// All intermediates stored as tf32 bit patterns (uint32)
__device__ uint32_t g_xt[(size_t)ROWS*DM];
__device__ uint32_t g_wq[(size_t)NH*DM*DH];
__device__ uint32_t g_wk[(size_t)NH*DM*DH];
__device__ uint32_t g_wv[(size_t)NH*DM*DH];
__device__ uint32_t g_wo[(size_t)DM*DM];
__device__ uint32_t g_q[(size_t)BATCH*NH*SEQ*DH];
__device__ uint32_t g_k[(size_t)BATCH*NH*SEQ*DH];
__device__ uint32_t g_v[(size_t)BATCH*NH*SEQ*DH];
__device__ uint32_t g_z[(size_t)ROWS*DM];

__device__ __forceinline__ uint32_t f2tf(float f) {
    uint32_t u;
    asm("cvt.rna.tf32.f32 %0, %1;" : "=r"(u) : "f"(f));
    return u;
}
__device__ __forceinline__ void mma8(float* d, const uint32_t* a, const uint32_t* b) {
    asm volatile(
        "mma.sync.aligned.m16n8k8.row.col.f32.tf32.tf32.f32 "
        "{%0,%1,%2,%3}, {%4,%5,%6,%7}, {%8,%9}, {%0,%1,%2,%3};\n"
        : "+f"(d[0]), "+f"(d[1]), "+f"(d[2]), "+f"(d[3])
        : "r"(a[0]), "r"(a[1]), "r"(a[2]), "r"(a[3]), "r"(b[0]), "r"(b[1]));
}
__device__ __forceinline__ void ldsm4(uint32_t* r, uint32_t addr) {
    asm volatile("ldmatrix.sync.aligned.m8n8.x4.shared.b16 {%0,%1,%2,%3}, [%4];"
        : "=r"(r[0]), "=r"(r[1]), "=r"(r[2]), "=r"(r[3]) : "r"(addr));
}
__device__ __forceinline__ uint32_t su32(const void* p) {
    return (uint32_t)__cvta_generic_to_shared(p);
}
#define CPA(dst, src) asm volatile("cp.async.cg.shared.global [%0], [%1], 16;" :: "r"(dst), "l"(src))
#define CPC() asm volatile("cp.async.commit_group;")
#define CPW1() asm volatile("cp.async.wait_group 1;")
#define CPW0() asm volatile("cp.async.wait_group 0;")

// ---------------------------------------------------------------------------
// Prep: convert fp32 -> tf32 bits. sel: 0=x 1=wq 2=wk 3=wv 4=wo
// ---------------------------------------------------------------------------
__global__ void __launch_bounds__(256) cvt_kernel(const float4* __restrict__ in, int sel, int n4)
{
    uint4* out = (sel == 0) ? (uint4*)g_xt : (sel == 1) ? (uint4*)g_wq :
                 (sel == 2) ? (uint4*)g_wk : (sel == 3) ? (uint4*)g_wv : (uint4*)g_wo;
    int i = blockIdx.x * 256 + threadIdx.x;
    if (i < n4) {
        float4 v = in[i];
        uint4 o;
        o.x = f2tf(v.x); o.y = f2tf(v.y); o.z = f2tf(v.z); o.w = f2tf(v.w);
        out[i] = o;
    }
}

// ===========================================================================
// GEMM: C[128x128], 128 threads (4 warps, 64x64 each), BK=32, 2-stage.
// A pitch 36, B pitch 136. A-frags via ldmatrix.x4, no cvt (inputs tf32 bits).
// ===========================================================================
#define AP 36
#define BP 136
#define A_ST (128*AP)
#define B_ST (32*BP)
#define GEMM_SMEM ((2*A_ST + 2*B_ST) * 4)

template <typename FB>
__device__ __forceinline__ void gemm128(const uint32_t* __restrict__ Ag, int lda,
                                        FB bsrc, int ntiles,
                                        uint32_t* As, uint32_t* Bs, float acc[4][8][4])
{
    const int tid = threadIdx.x;
    const int lane = tid & 31, wid = tid >> 5;
    const int wm = wid >> 1, wn = wid & 1;
    const int lq = lane >> 2, lr = lane & 3;
    const int lrow = lane & 15, lcol = (lane >> 4) * 4;

    auto load_tile = [&](int t, int s) {
        #pragma unroll
        for (int i = 0; i < 8; i++) {
            int idx = tid + i * 128;
            int r = idx >> 3, c4 = idx & 7;
            CPA(su32(&As[s*A_ST + r*AP + c4*4]), Ag + (size_t)r * lda + t*32 + c4*4);
        }
        #pragma unroll
        for (int i = 0; i < 8; i++) {
            int idx = tid + i * 128;
            int kr = idx >> 5, c4 = idx & 31;
            CPA(su32(&Bs[s*B_ST + kr*BP + c4*4]), bsrc(t*32 + kr, c4));
        }
    };

    load_tile(0, 0); CPC();

    for (int t = 0; t < ntiles; t++) {
        if (t + 1 < ntiles) { load_tile(t + 1, (t + 1) & 1); CPC(); CPW1(); }
        else { CPW0(); }
        __syncthreads();

        const uint32_t* A_ = As + (t & 1) * A_ST;
        const uint32_t* B_ = Bs + (t & 1) * B_ST;
        #pragma unroll
        for (int kc = 0; kc < 4; kc++) {
            uint32_t a[4][4], b[8][2];
            #pragma unroll
            for (int mt = 0; mt < 4; mt++)
                ldsm4(a[mt], su32(&A_[(wm*64 + mt*16 + lrow)*AP + kc*8 + lcol]));
            #pragma unroll
            for (int nt = 0; nt < 8; nt++) {
                int col = wn*64 + nt*8 + lq;
                b[nt][0] = B_[(kc*8 + lr)*BP + col];
                b[nt][1] = B_[(kc*8 + 4 + lr)*BP + col];
            }
            #pragma unroll
            for (int mt = 0; mt < 4; mt++)
                #pragma unroll
                for (int nt = 0; nt < 8; nt++)
                    mma8(acc[mt][nt], a[mt], b[nt]);
        }
        __syncthreads();
    }
}

// ---------------------------------------------------------------------------
// Kernel 1: fused QKV. grid=(ROWS/128, 18), block=128. Writes tf32 bits.
// ---------------------------------------------------------------------------
__global__ void __launch_bounds__(128) qkv_kernel(
    const float* __restrict__ bq, const float* __restrict__ bk,
    const float* __restrict__ bv)
{
    extern __shared__ uint32_t smu[];
    uint32_t* As = smu;
    uint32_t* Bs = smu + 2*A_ST;

    const int nb = blockIdx.y;
    const int sel = nb / 6;
    const int h0 = (nb % 6) * 2;
    const uint32_t* W   = (sel == 0) ? g_wq : ((sel == 1) ? g_wk : g_wv);
    const float* bias   = (sel == 0) ? bq : ((sel == 1) ? bk : bv);
    uint32_t* out       = (sel == 0) ? g_q : ((sel == 1) ? g_k : g_v);

    const int row0 = blockIdx.x * 128;

    float acc[4][8][4] = {};
    auto bsrc = [&](int k, int c4) {
        int head = h0 + (c4 >> 4);
        return W + (size_t)head * DM * DH + (size_t)k * DH + (c4 & 15) * 4;
    };
    gemm128(g_xt + (size_t)row0 * DM, DM, bsrc, DM/32, As, Bs, acc);

    const int tid = threadIdx.x, lane = tid & 31, wid = tid >> 5;
    const int wm = wid >> 1, wn = wid & 1, lq = lane >> 2, lr = lane & 3;

    #pragma unroll
    for (int mt = 0; mt < 4; mt++) {
        #pragma unroll
        for (int nt = 0; nt < 8; nt++) {
            int c = wn*64 + nt*8 + 2*lr;
            int h = h0 + (c >> 6), d = c & 63;
            float bz0 = bias[h*DH + d], bz1 = bias[h*DH + d + 1];
            #pragma unroll
            for (int half = 0; half < 2; half++) {
                int gr = row0 + wm*64 + mt*16 + lq + half*8;
                int bb = gr / SEQ, s = gr % SEQ;
                size_t base = (((size_t)bb*NH + h)*SEQ + s)*DH + d;
                out[base]     = f2tf(acc[mt][nt][half*2+0] + bz0);
                out[base + 1] = f2tf(acc[mt][nt][half*2+1] + bz1);
            }
        }
    }
}

// ---------------------------------------------------------------------------
// Kernel 3: output projection. grid=(ROWS/128, 6), block=128. fp32 out.
// ---------------------------------------------------------------------------
__global__ void __launch_bounds__(128) oproj_kernel(
    const float* __restrict__ bo, float* __restrict__ out)
{
    extern __shared__ uint32_t smu[];
    uint32_t* As = smu;
    uint32_t* Bs = smu + 2*A_ST;

    const int row0 = blockIdx.x * 128;
    const int n0   = blockIdx.y * 128;

    float acc[4][8][4] = {};
    auto bsrc = [&](int k, int c4) {
        return g_wo + (size_t)k * DM + n0 + c4 * 4;
    };
    gemm128(g_z + (size_t)row0 * DM, DM, bsrc, DM/32, As, Bs, acc);

    const int tid = threadIdx.x, lane = tid & 31, wid = tid >> 5;
    const int wm = wid >> 1, wn = wid & 1, lq = lane >> 2, lr = lane & 3;

    #pragma unroll
    for (int mt = 0; mt < 4; mt++) {
        #pragma unroll
        for (int nt = 0; nt < 8; nt++) {
            int c = n0 + wn*64 + nt*8 + 2*lr;
            float bz0 = bo[c], bz1 = bo[c + 1];
            #pragma unroll
            for (int half = 0; half < 2; half++) {
                size_t orow = (size_t)(row0 + wm*64 + mt*16 + lq + half*8) * DM;
                out[orow + c]     = acc[mt][nt][half*2+0] + bz0;
                out[orow + c + 1] = acc[mt][nt][half*2+1] + bz1;
            }
        }
    }
}

// ===========================================================================
// Kernel 2: causal flash attention. grid=(SEQ/256, NH, BATCH), block=256.
// 8 warps x 32 q-rows, k-tile 64, cp.async 2-stage, ldmatrix for Q/P frags.
// ===========================================================================
#define QTILE 256
#define QP 68
#define KP 68
#define VP 72
#define K_ST (64*KP)
#define V_ST (64*VP)
#define Q_OFF 0
#define P_OFF (QTILE*QP)
#define K_OFF (2*QTILE*QP)
#define V_OFF (K_OFF + 2*K_ST)
#define FLASH_SMEM ((2*QTILE*QP + 2*K_ST + 2*V_ST) * 4)

__global__ void __launch_bounds__(256) flash_kernel()
{
    extern __shared__ uint32_t smu[];
    uint32_t* Qs = smu + Q_OFF;
    uint32_t* Ps = smu + P_OFF;

    const int qt = (int)gridDim.x - 1 - (int)blockIdx.x;  // big diagonals first
    const int h  = blockIdx.y;
    const int b  = blockIdx.z;
    const int q0 = qt * QTILE;

    const size_t hb = ((size_t)b * NH + h) * SEQ * DH;
    const uint32_t* qp = g_q + hb;
    const uint32_t* kp = g_k + hb;
    const uint32_t* vp = g_v + hb;

    const int tid  = threadIdx.x;
    const int lane = tid & 31;
    const int wid  = tid >> 5;
    const int lq   = lane >> 2, lr = lane & 3;
    const int lrow = lane & 15, lcol = (lane >> 4) * 4;
    const int wbase = wid * 32;

    auto loadKV = [&](int kt, int s) {
        int k0 = kt * 64;
        #pragma unroll
        for (int i = 0; i < 4; i++) {
            int idx = tid + i * 256;
            int r = idx >> 4, c4 = idx & 15;
            CPA(su32(&smu[K_OFF + s*K_ST + r*KP + c4*4]), kp + (size_t)(k0+r)*DH + c4*4);
            CPA(su32(&smu[V_OFF + s*V_ST + r*VP + c4*4]), vp + (size_t)(k0+r)*DH + c4*4);
        }
    };

    #pragma unroll
    for (int i = 0; i < 16; i++) {
        int idx = tid + i * 256;
        int r = idx >> 4, c4 = idx & 15;
        CPA(su32(&Qs[r*QP + c4*4]), qp + (size_t)(q0+r)*DH + c4*4);
    }
    loadKV(0, 0);
    CPC();

    float o[2][8][4] = {};
    float mrow[2][2], lrow2[2][2];
    #pragma unroll
    for (int mt = 0; mt < 2; mt++) { mrow[mt][0]=-INFINITY; mrow[mt][1]=-INFINITY; lrow2[mt][0]=0.f; lrow2[mt][1]=0.f; }

    const int nkt = 4*qt + 4;
    for (int kt = 0; kt < nkt; kt++) {
        if (kt + 1 < nkt) { loadKV(kt + 1, (kt + 1) & 1); CPC(); CPW1(); }
        else { CPW0(); }
        __syncthreads();

        const int k0 = kt * 64;
        const uint32_t* K_ = smu + K_OFF + (kt & 1) * K_ST;
        const uint32_t* V_ = smu + V_OFF + (kt & 1) * V_ST;

        // S = Q @ K^T : warp tile 32(q) x 64(k)
        float sf[2][8][4] = {};
        #pragma unroll
        for (int kc = 0; kc < 8; kc++) {
            uint32_t a[2][4];
            #pragma unroll
            for (int mt = 0; mt < 2; mt++)
                ldsm4(a[mt], su32(&Qs[(wbase + mt*16 + lrow)*QP + kc*8 + lcol]));
            #pragma unroll
            for (int nt = 0; nt < 8; nt++) {
                int key = nt*8 + lq;
                uint32_t bb2[2];
                bb2[0] = K_[key*KP + kc*8 + lr];
                bb2[1] = K_[key*KP + kc*8 + 4 + lr];
                mma8(sf[0][nt], a[0], bb2);
                mma8(sf[1][nt], a[1], bb2);
            }
        }

        // scale + causal mask
        const bool nm = (k0 + 63 > q0 + wbase);
        #pragma unroll
        for (int mt = 0; mt < 2; mt++) {
            int grow0 = q0 + wbase + mt*16 + lq;
            #pragma unroll
            for (int nt = 0; nt < 8; nt++) {
                #pragma unroll
                for (int e = 0; e < 4; e++) {
                    float v = sf[mt][nt][e] * 0.125f;
                    if (nm) {
                        int gc = k0 + nt*8 + 2*lr + (e & 1);
                        int grow = grow0 + ((e >= 2) ? 8 : 0);
                        if (gc > grow) v = -1e30f;
                    }
                    sf[mt][nt][e] = v;
                }
            }
        }

        // online softmax (rows lq, lq+8 per quad)
        #pragma unroll
        for (int mt = 0; mt < 2; mt++) {
            float t0 = -INFINITY, t1 = -INFINITY;
            #pragma unroll
            for (int nt = 0; nt < 8; nt++) {
                t0 = fmaxf(t0, fmaxf(sf[mt][nt][0], sf[mt][nt][1]));
                t1 = fmaxf(t1, fmaxf(sf[mt][nt][2], sf[mt][nt][3]));
            }
            t0 = fmaxf(t0, __shfl_xor_sync(0xffffffffu, t0, 1));
            t0 = fmaxf(t0, __shfl_xor_sync(0xffffffffu, t0, 2));
            t1 = fmaxf(t1, __shfl_xor_sync(0xffffffffu, t1, 1));
            t1 = fmaxf(t1, __shfl_xor_sync(0xffffffffu, t1, 2));

            float mn0 = fmaxf(mrow[mt][0], t0), mn1 = fmaxf(mrow[mt][1], t1);
            float sc0 = __expf(mrow[mt][0] - mn0), sc1 = __expf(mrow[mt][1] - mn1);
            mrow[mt][0] = mn0; mrow[mt][1] = mn1;

            float s0 = 0.f, s1 = 0.f;
            int rA = wbase + mt*16 + lq;
            #pragma unroll
            for (int nt = 0; nt < 8; nt++) {
                float p0 = __expf(sf[mt][nt][0] - mn0);
                float p1 = __expf(sf[mt][nt][1] - mn0);
                float p2 = __expf(sf[mt][nt][2] - mn1);
                float p3 = __expf(sf[mt][nt][3] - mn1);
                s0 += p0 + p1; s1 += p2 + p3;
                int col = nt*8 + 2*lr;
                Ps[rA*QP + col]         = f2tf(p0);
                Ps[rA*QP + col + 1]     = f2tf(p1);
                Ps[(rA+8)*QP + col]     = f2tf(p2);
                Ps[(rA+8)*QP + col + 1] = f2tf(p3);
            }
            s0 += __shfl_xor_sync(0xffffffffu, s0, 1);
            s0 += __shfl_xor_sync(0xffffffffu, s0, 2);
            s1 += __shfl_xor_sync(0xffffffffu, s1, 1);
            s1 += __shfl_xor_sync(0xffffffffu, s1, 2);
            lrow2[mt][0] = lrow2[mt][0] * sc0 + s0;
            lrow2[mt][1] = lrow2[mt][1] * sc1 + s1;

            #pragma unroll
            for (int nt = 0; nt < 8; nt++) {
                o[mt][nt][0] *= sc0; o[mt][nt][1] *= sc0;
                o[mt][nt][2] *= sc1; o[mt][nt][3] *= sc1;
            }
        }
        __syncwarp();

        // O += P @ V : 32(q) x 64(dh) over 64 keys
        #pragma unroll
        for (int kc = 0; kc < 8; kc++) {
            uint32_t a[2][4];
            #pragma unroll
            for (int mt = 0; mt < 2; mt++)
                ldsm4(a[mt], su32(&Ps[(wbase + mt*16 + lrow)*QP + kc*8 + lcol]));
            #pragma unroll
            for (int nt = 0; nt < 8; nt++) {
                uint32_t bb2[2];
                bb2[0] = V_[(kc*8+lr)*VP + nt*8 + lq];
                bb2[1] = V_[(kc*8+4+lr)*VP + nt*8 + lq];
                mma8(o[0][nt], a[0], bb2);
                mma8(o[1][nt], a[1], bb2);
            }
        }
        __syncwarp();
        __syncthreads();
    }

    #pragma unroll
    for (int mt = 0; mt < 2; mt++) {
        float inv0 = 1.f / lrow2[mt][0], inv1 = 1.f / lrow2[mt][1];
        size_t r0 = (size_t)b * SEQ + q0 + wbase + mt*16 + lq;
        #pragma unroll
        for (int nt = 0; nt < 8; nt++) {
            int col = h*DH + nt*8 + 2*lr;
            g_z[r0 * DM + col]           = f2tf(o[mt][nt][0] * inv0);
            g_z[r0 * DM + col + 1]       = f2tf(o[mt][nt][1] * inv0);
            g_z[(r0 + 8) * DM + col]     = f2tf(o[mt][nt][2] * inv1);
            g_z[(r0 + 8) * DM + col + 1] = f2tf(o[mt][nt][3] * inv1);
        }
    }
}

extern "C" void kernel_launch(void* const* d_in, const int* in_sizes, int n_in,
                              void* d_out, int out_size)
{
    const float* x  = (const float*)d_in[0];
    const float* Wq = (const float*)d_in[1];
    const float* Wk = (const float*)d_in[2];
    const float* Wv = (const float*)d_in[3];
    const float* Wo = (const float*)d_in[4];
    const float* bq = (const float*)d_in[5];
    const float* bk = (const float*)d_in[6];
    const float* bv = (const float*)d_in[7];
    const float* bo = (const float*)d_in[8];
    float* out = (float*)d_out;

    cudaFuncSetAttribute(qkv_kernel,   cudaFuncAttributeMaxDynamicSharedMemorySize, GEMM_SMEM);
    cudaFuncSetAttribute(oproj_kernel, cudaFuncAttributeMaxDynamicSharedMemorySize, GEMM_SMEM);
    cudaFuncSetAttribute(flash_kernel, cudaFuncAttributeMaxDynamicSharedMemorySize, FLASH_SMEM);

    const int nx4 = ROWS*DM/4;          // 1,572,864
    const int nw4 = NH*DM*DH/4;         // 147,456
    const int no4 = DM*DM/4;            // 147,456
    cvt_kernel<<<nx4/256, 256>>>((const float4*)x,  0, nx4);
    cvt_kernel<<<nw4/256, 256>>>((const float4*)Wq, 1, nw4);
    cvt_kernel<<<nw4/256, 256>>>((const float4*)Wk, 2, nw4);
    cvt_kernel<<<nw4/256, 256>>>((const float4*)Wv, 3, nw4);
    cvt_kernel<<<no4/256, 256>>>((const float4*)Wo, 4, no4);

    qkv_kernel<<<dim3(ROWS / 128, 18), 128, GEMM_SMEM>>>(bq, bk, bv);
    flash_kernel<<<dim3(SEQ / QTILE, NH, BATCH), 256, FLASH_SMEM>>>();
    oproj_kernel<<<dim3(ROWS / 128, 6), 128, GEMM_SMEM>>>(bo, out);
}

// round 8
// speedup vs baseline: 8.3543x; 1.6629x over previous
#include <cuda_runtime.h>
#include <cuda_fp16.h>
#include <math.h>
#include <stdint.h>

#define BATCH 4
#define SEQ 2048
#define DM 768
#define NH 12
#define DH 64
#define ROWS (BATCH*SEQ)

// fp16 intermediates
__device__ __half g_xh [(size_t)ROWS*DM];
__device__ __half g_wqh[(size_t)NH*DM*DH];   // [h][m][d]  (as given)
__device__ __half g_wkh[(size_t)NH*DM*DH];
__device__ __half g_wvh[(size_t)NH*DM*DH];
__device__ __half g_woh[(size_t)DM*DM];      // [hd][m] -> used as [k][n]
__device__ __half g_q[(size_t)BATCH*NH*SEQ*DH];  // pre-scaled by 0.125*log2e
__device__ __half g_k[(size_t)BATCH*NH*SEQ*DH];
__device__ __half g_v[(size_t)BATCH*NH*SEQ*DH];
__device__ __half g_zh[(size_t)ROWS*DM];

#define QSC 0.1803368801111154f  /* 0.125 * log2(e) */

__device__ __forceinline__ float ex2f(float x) {
    float y; asm("ex2.approx.f32 %0, %1;" : "=f"(y) : "f"(x)); return y;
}
__device__ __forceinline__ void mma16(float* d, const uint32_t* a, const uint32_t* b) {
    asm volatile(
        "mma.sync.aligned.m16n8k16.row.col.f32.f16.f16.f32 "
        "{%0,%1,%2,%3}, {%4,%5,%6,%7}, {%8,%9}, {%0,%1,%2,%3};\n"
        : "+f"(d[0]), "+f"(d[1]), "+f"(d[2]), "+f"(d[3])
        : "r"(a[0]), "r"(a[1]), "r"(a[2]), "r"(a[3]), "r"(b[0]), "r"(b[1]));
}
__device__ __forceinline__ void ldsm4(uint32_t* r, uint32_t addr) {
    asm volatile("ldmatrix.sync.aligned.m8n8.x4.shared.b16 {%0,%1,%2,%3}, [%4];"
        : "=r"(r[0]), "=r"(r[1]), "=r"(r[2]), "=r"(r[3]) : "r"(addr));
}
__device__ __forceinline__ void ldsm4t(uint32_t* r, uint32_t addr) {
    asm volatile("ldmatrix.sync.aligned.m8n8.x4.trans.shared.b16 {%0,%1,%2,%3}, [%4];"
        : "=r"(r[0]), "=r"(r[1]), "=r"(r[2]), "=r"(r[3]) : "r"(addr));
}
__device__ __forceinline__ uint32_t su32(const void* p) {
    return (uint32_t)__cvta_generic_to_shared(p);
}
#define CPA(dst, src) asm volatile("cp.async.cg.shared.global [%0], [%1], 16;" :: "r"(dst), "l"(src))
#define CPC() asm volatile("cp.async.commit_group;")
#define CPW1() asm volatile("cp.async.wait_group 1;")
#define CPW0() asm volatile("cp.async.wait_group 0;")

// ---------------------------------------------------------------------------
// Prep: fp32 -> fp16. sel: 0=x 1=wq 2=wk 3=wv 4=wo
// ---------------------------------------------------------------------------
__global__ void __launch_bounds__(256) cvt_kernel(const float4* __restrict__ in, int sel, int n4)
{
    __half2* out = (sel == 0) ? (__half2*)g_xh : (sel == 1) ? (__half2*)g_wqh :
                   (sel == 2) ? (__half2*)g_wkh : (sel == 3) ? (__half2*)g_wvh : (__half2*)g_woh;
    int i = blockIdx.x * 256 + threadIdx.x;
    if (i < n4) {
        float4 v = in[i];
        out[2*i]   = __floats2half2_rn(v.x, v.y);
        out[2*i+1] = __floats2half2_rn(v.z, v.w);
    }
}

// ===========================================================================
// GEMM: C[128x128] = A[128xK] @ B[Kx128] (fp16 in, fp32 acc). 128 threads,
// 4 warps (64x64 each), BK=32, 2-stage cp.async.
// A smem [128 x 32] pitch 40 halfs; B smem [32 x 128] pitch 136 halfs.
// A-frags ldmatrix.x4; B-frags ldmatrix.x4.trans (B is [k][n] row-major).
// ===========================================================================
#define APh 40
#define BPh 136
#define A_STh (128*APh)
#define B_STh (32*BPh)
#define GEMM_SMEM ((2*A_STh + 2*B_STh) * 2)

template <typename FB>
__device__ __forceinline__ void gemm128h(const __half* __restrict__ Ag,
                                         FB bsrc, int ntiles,
                                         __half* As, __half* Bs, float acc[4][8][4])
{
    const int tid = threadIdx.x;
    const int lane = tid & 31, wid = tid >> 5;
    const int wm = wid >> 1, wn = wid & 1;
    const int lrow = lane & 15, lch = (lane >> 4) * 8;
    const int j8 = lane >> 3, i8 = lane & 7;

    auto load_tile = [&](int t, int s) {
        #pragma unroll
        for (int i = 0; i < 4; i++) {
            int id = tid + i * 128;
            int r = id >> 2, c8 = id & 3;
            CPA(su32(&As[s*A_STh + r*APh + c8*8]), Ag + (size_t)r * DM + t*32 + c8*8);
        }
        #pragma unroll
        for (int i = 0; i < 4; i++) {
            int id = tid + i * 128;
            int kr = id >> 4, c8 = id & 15;
            CPA(su32(&Bs[s*B_STh + kr*BPh + c8*8]), bsrc(t*32 + kr, c8));
        }
    };

    load_tile(0, 0); CPC();

    for (int t = 0; t < ntiles; t++) {
        if (t + 1 < ntiles) { load_tile(t + 1, (t + 1) & 1); CPC(); CPW1(); }
        else { CPW0(); }
        __syncthreads();

        const __half* A_ = As + (t & 1) * A_STh;
        const __half* B_ = Bs + (t & 1) * B_STh;
        #pragma unroll
        for (int kc = 0; kc < 2; kc++) {
            uint32_t a[4][4], b[8][2];
            #pragma unroll
            for (int mt = 0; mt < 4; mt++)
                ldsm4(a[mt], su32(&A_[(wm*64 + mt*16 + lrow)*APh + kc*16 + lch]));
            #pragma unroll
            for (int ntp = 0; ntp < 4; ntp++) {
                uint32_t r4[4];
                ldsm4t(r4, su32(&B_[(kc*16 + (j8&1)*8 + i8)*BPh + wn*64 + ntp*16 + (j8>>1)*8]));
                b[2*ntp][0]   = r4[0]; b[2*ntp][1]   = r4[1];
                b[2*ntp+1][0] = r4[2]; b[2*ntp+1][1] = r4[3];
            }
            #pragma unroll
            for (int mt = 0; mt < 4; mt++)
                #pragma unroll
                for (int nt = 0; nt < 8; nt++)
                    mma16(acc[mt][nt], a[mt], b[nt]);
        }
        __syncthreads();
    }
}

// ---------------------------------------------------------------------------
// Kernel 1: fused QKV. grid=(ROWS/128, 18), block=128.
// sel = y/6, heads h0=(y%6)*2 (N=128 = 2 heads). Q scaled by QSC at write.
// ---------------------------------------------------------------------------
__global__ void __launch_bounds__(128) qkv_kernel(
    const float* __restrict__ bq, const float* __restrict__ bk,
    const float* __restrict__ bv)
{
    extern __shared__ __half smh[];
    __half* As = smh;
    __half* Bs = smh + 2*A_STh;

    const int nb = blockIdx.y;
    const int sel = nb / 6;
    const int h0 = (nb % 6) * 2;
    const __half* W   = (sel == 0) ? g_wqh : ((sel == 1) ? g_wkh : g_wvh);
    const float* bias = (sel == 0) ? bq : ((sel == 1) ? bk : bv);
    __half* out       = (sel == 0) ? g_q : ((sel == 1) ? g_k : g_v);
    const float osc   = (sel == 0) ? QSC : 1.0f;

    const int row0 = blockIdx.x * 128;

    float acc[4][8][4] = {};
    auto bsrc = [&](int k, int c8) {
        return W + ((size_t)(h0 + (c8 >> 3)) * DM + k) * DH + (c8 & 7) * 8;
    };
    gemm128h(g_xh + (size_t)row0 * DM, bsrc, DM/32, As, Bs, acc);

    const int tid = threadIdx.x, lane = tid & 31, wid = tid >> 5;
    const int wm = wid >> 1, wn = wid & 1, lq = lane >> 2, lr = lane & 3;

    #pragma unroll
    for (int mt = 0; mt < 4; mt++) {
        #pragma unroll
        for (int nt = 0; nt < 8; nt++) {
            int c = wn*64 + nt*8 + 2*lr;
            int h = h0 + (c >> 6), d = c & 63;
            float bz0 = bias[h*DH + d], bz1 = bias[h*DH + d + 1];
            #pragma unroll
            for (int half_ = 0; half_ < 2; half_++) {
                int gr = row0 + wm*64 + mt*16 + lq + half_*8;
                int bb = gr / SEQ, s = gr % SEQ;
                size_t base = (((size_t)bb*NH + h)*SEQ + s)*DH + d;
                *(__half2*)(out + base) = __floats2half2_rn(
                    (acc[mt][nt][half_*2+0] + bz0) * osc,
                    (acc[mt][nt][half_*2+1] + bz1) * osc);
            }
        }
    }
}

// ---------------------------------------------------------------------------
// Kernel 3: output projection. grid=(ROWS/128, 6), block=128. fp32 out.
// ---------------------------------------------------------------------------
__global__ void __launch_bounds__(128) oproj_kernel(
    const float* __restrict__ bo, float* __restrict__ out)
{
    extern __shared__ __half smh[];
    __half* As = smh;
    __half* Bs = smh + 2*A_STh;

    const int row0 = blockIdx.x * 128;
    const int n0   = blockIdx.y * 128;

    float acc[4][8][4] = {};
    auto bsrc = [&](int k, int c8) {
        return g_woh + (size_t)k * DM + n0 + c8 * 8;
    };
    gemm128h(g_zh + (size_t)row0 * DM, bsrc, DM/32, As, Bs, acc);

    const int tid = threadIdx.x, lane = tid & 31, wid = tid >> 5;
    const int wm = wid >> 1, wn = wid & 1, lq = lane >> 2, lr = lane & 3;

    #pragma unroll
    for (int mt = 0; mt < 4; mt++) {
        #pragma unroll
        for (int nt = 0; nt < 8; nt++) {
            int c = n0 + wn*64 + nt*8 + 2*lr;
            float bz0 = bo[c], bz1 = bo[c + 1];
            #pragma unroll
            for (int half_ = 0; half_ < 2; half_++) {
                size_t orow = (size_t)(row0 + wm*64 + mt*16 + lq + half_*8) * DM;
                out[orow + c]     = acc[mt][nt][half_*2+0] + bz0;
                out[orow + c + 1] = acc[mt][nt][half_*2+1] + bz1;
            }
        }
    }
}

// ===========================================================================
// Kernel 2: causal flash attention, fp16. grid=(SEQ/256, NH, BATCH), block=256.
// 8 warps x 32 q-rows, k-tile 64, 2-stage cp.async. S in log2 domain
// (Q pre-scaled), ex2 softmax. Pitches 72 halfs (conflict-free ldmatrix).
// ===========================================================================
#define QTILE 256
#define QPh 72
#define K_STh (64*QPh)
#define Q_OFFh 0
#define P_OFFh (QTILE*QPh)
#define K_OFFh (2*QTILE*QPh)
#define V_OFFh (K_OFFh + 2*K_STh)
#define FLASH_SMEM ((2*QTILE*QPh + 4*K_STh) * 2)

__global__ void __launch_bounds__(256) flash_kernel()
{
    extern __shared__ __half smh[];
    __half* Qs = smh + Q_OFFh;
    __half* Ps = smh + P_OFFh;

    const int qt = (int)gridDim.x - 1 - (int)blockIdx.x;
    const int h  = blockIdx.y;
    const int b  = blockIdx.z;
    const int q0 = qt * QTILE;

    const size_t hb = ((size_t)b * NH + h) * SEQ * DH;
    const __half* qp = g_q + hb;
    const __half* kp = g_k + hb;
    const __half* vp = g_v + hb;

    const int tid  = threadIdx.x;
    const int lane = tid & 31;
    const int wid  = tid >> 5;
    const int lq   = lane >> 2, lr = lane & 3;
    const int lrow = lane & 15, lch = (lane >> 4) * 8;
    const int j8 = lane >> 3, i8 = lane & 7;
    const int wbase = wid * 32;

    auto loadKV = [&](int kt, int s) {
        int k0 = kt * 64;
        #pragma unroll
        for (int i = 0; i < 2; i++) {
            int id = tid + i * 256;
            int r = id >> 3, c8 = id & 7;
            CPA(su32(&smh[K_OFFh + s*K_STh + r*QPh + c8*8]), kp + (size_t)(k0+r)*DH + c8*8);
            CPA(su32(&smh[V_OFFh + s*K_STh + r*QPh + c8*8]), vp + (size_t)(k0+r)*DH + c8*8);
        }
    };

    #pragma unroll
    for (int i = 0; i < 8; i++) {
        int id = tid + i * 256;
        int r = id >> 3, c8 = id & 7;
        CPA(su32(&Qs[r*QPh + c8*8]), qp + (size_t)(q0+r)*DH + c8*8);
    }
    loadKV(0, 0);
    CPC();

    float o[2][8][4] = {};
    float mrow[2][2], lrow2[2][2];
    #pragma unroll
    for (int mt = 0; mt < 2; mt++) { mrow[mt][0]=-INFINITY; mrow[mt][1]=-INFINITY; lrow2[mt][0]=0.f; lrow2[mt][1]=0.f; }

    const int nkt = 4*qt + 4;
    for (int kt = 0; kt < nkt; kt++) {
        if (kt + 1 < nkt) { loadKV(kt + 1, (kt + 1) & 1); CPC(); CPW1(); }
        else { CPW0(); }
        __syncthreads();

        const int k0 = kt * 64;
        const __half* K_ = smh + K_OFFh + (kt & 1) * K_STh;
        const __half* V_ = smh + V_OFFh + (kt & 1) * K_STh;

        // S = Q @ K^T (log2 domain): warp 32(q) x 64(k), kc over d (4 x k16)
        float sf[2][8][4] = {};
        #pragma unroll
        for (int kc = 0; kc < 4; kc++) {
            uint32_t a[2][4], bk2[8][2];
            #pragma unroll
            for (int mt = 0; mt < 2; mt++)
                ldsm4(a[mt], su32(&Qs[(wbase + mt*16 + lrow)*QPh + kc*16 + lch]));
            #pragma unroll
            for (int ntp = 0; ntp < 4; ntp++) {
                uint32_t r4[4];
                ldsm4(r4, su32(&K_[(ntp*16 + (j8>>1)*8 + i8)*QPh + kc*16 + (j8&1)*8]));
                bk2[2*ntp][0]   = r4[0]; bk2[2*ntp][1]   = r4[1];
                bk2[2*ntp+1][0] = r4[2]; bk2[2*ntp+1][1] = r4[3];
            }
            #pragma unroll
            for (int nt = 0; nt < 8; nt++) {
                mma16(sf[0][nt], a[0], bk2[nt]);
                mma16(sf[1][nt], a[1], bk2[nt]);
            }
        }

        // causal mask (S already scaled via Q)
        const bool nm = (k0 + 63 > q0 + wbase);
        if (nm) {
            #pragma unroll
            for (int mt = 0; mt < 2; mt++) {
                int grow0 = q0 + wbase + mt*16 + lq;
                #pragma unroll
                for (int nt = 0; nt < 8; nt++) {
                    #pragma unroll
                    for (int e = 0; e < 4; e++) {
                        int gc = k0 + nt*8 + 2*lr + (e & 1);
                        int grow = grow0 + ((e >= 2) ? 8 : 0);
                        if (gc > grow) sf[mt][nt][e] = -1e30f;
                    }
                }
            }
        }

        // online softmax (base-2)
        #pragma unroll
        for (int mt = 0; mt < 2; mt++) {
            float t0 = -INFINITY, t1 = -INFINITY;
            #pragma unroll
            for (int nt = 0; nt < 8; nt++) {
                t0 = fmaxf(t0, fmaxf(sf[mt][nt][0], sf[mt][nt][1]));
                t1 = fmaxf(t1, fmaxf(sf[mt][nt][2], sf[mt][nt][3]));
            }
            t0 = fmaxf(t0, __shfl_xor_sync(0xffffffffu, t0, 1));
            t0 = fmaxf(t0, __shfl_xor_sync(0xffffffffu, t0, 2));
            t1 = fmaxf(t1, __shfl_xor_sync(0xffffffffu, t1, 1));
            t1 = fmaxf(t1, __shfl_xor_sync(0xffffffffu, t1, 2));

            float mn0 = fmaxf(mrow[mt][0], t0), mn1 = fmaxf(mrow[mt][1], t1);
            float sc0 = ex2f(mrow[mt][0] - mn0), sc1 = ex2f(mrow[mt][1] - mn1);
            mrow[mt][0] = mn0; mrow[mt][1] = mn1;

            float s0 = 0.f, s1 = 0.f;
            int rA = wbase + mt*16 + lq;
            #pragma unroll
            for (int nt = 0; nt < 8; nt++) {
                float p0 = ex2f(sf[mt][nt][0] - mn0);
                float p1 = ex2f(sf[mt][nt][1] - mn0);
                float p2 = ex2f(sf[mt][nt][2] - mn1);
                float p3 = ex2f(sf[mt][nt][3] - mn1);
                s0 += p0 + p1; s1 += p2 + p3;
                int col = nt*8 + 2*lr;
                *(__half2*)&Ps[rA*QPh + col]     = __floats2half2_rn(p0, p1);
                *(__half2*)&Ps[(rA+8)*QPh + col] = __floats2half2_rn(p2, p3);
            }
            s0 += __shfl_xor_sync(0xffffffffu, s0, 1);
            s0 += __shfl_xor_sync(0xffffffffu, s0, 2);
            s1 += __shfl_xor_sync(0xffffffffu, s1, 1);
            s1 += __shfl_xor_sync(0xffffffffu, s1, 2);
            lrow2[mt][0] = lrow2[mt][0] * sc0 + s0;
            lrow2[mt][1] = lrow2[mt][1] * sc1 + s1;

            #pragma unroll
            for (int nt = 0; nt < 8; nt++) {
                o[mt][nt][0] *= sc0; o[mt][nt][1] *= sc0;
                o[mt][nt][2] *= sc1; o[mt][nt][3] *= sc1;
            }
        }
        __syncwarp();

        // O += P @ V : kc over keys (4 x k16); V-frags via trans ldmatrix
        #pragma unroll
        for (int kc = 0; kc < 4; kc++) {
            uint32_t a[2][4], bv2[8][2];
            #pragma unroll
            for (int mt = 0; mt < 2; mt++)
                ldsm4(a[mt], su32(&Ps[(wbase + mt*16 + lrow)*QPh + kc*16 + lch]));
            #pragma unroll
            for (int dp = 0; dp < 4; dp++) {
                uint32_t r4[4];
                ldsm4t(r4, su32(&V_[(kc*16 + (j8&1)*8 + i8)*QPh + dp*16 + (j8>>1)*8]));
                bv2[2*dp][0]   = r4[0]; bv2[2*dp][1]   = r4[1];
                bv2[2*dp+1][0] = r4[2]; bv2[2*dp+1][1] = r4[3];
            }
            #pragma unroll
            for (int nt = 0; nt < 8; nt++) {
                mma16(o[0][nt], a[0], bv2[nt]);
                mma16(o[1][nt], a[1], bv2[nt]);
            }
        }
        __syncwarp();
        __syncthreads();
    }

    #pragma unroll
    for (int mt = 0; mt < 2; mt++) {
        float inv0 = 1.f / lrow2[mt][0], inv1 = 1.f / lrow2[mt][1];
        size_t r0 = (size_t)b * SEQ + q0 + wbase + mt*16 + lq;
        #pragma unroll
        for (int nt = 0; nt < 8; nt++) {
            int col = h*DH + nt*8 + 2*lr;
            *(__half2*)&g_zh[r0 * DM + col] =
                __floats2half2_rn(o[mt][nt][0] * inv0, o[mt][nt][1] * inv0);
            *(__half2*)&g_zh[(r0 + 8) * DM + col] =
                __floats2half2_rn(o[mt][nt][2] * inv1, o[mt][nt][3] * inv1);
        }
    }
}

extern "C" void kernel_launch(void* const* d_in, const int* in_sizes, int n_in,
                              void* d_out, int out_size)
{
    const float* x  = (const float*)d_in[0];
    const float* Wq = (const float*)d_in[1];
    const float* Wk = (const float*)d_in[2];
    const float* Wv = (const float*)d_in[3];
    const float* Wo = (const float*)d_in[4];
    const float* bq = (const float*)d_in[5];
    const float* bk = (const float*)d_in[6];
    const float* bv = (const float*)d_in[7];
    const float* bo = (const float*)d_in[8];
    float* out = (float*)d_out;

    cudaFuncSetAttribute(qkv_kernel,   cudaFuncAttributeMaxDynamicSharedMemorySize, GEMM_SMEM);
    cudaFuncSetAttribute(oproj_kernel, cudaFuncAttributeMaxDynamicSharedMemorySize, GEMM_SMEM);
    cudaFuncSetAttribute(flash_kernel, cudaFuncAttributeMaxDynamicSharedMemorySize, FLASH_SMEM);

    const int nx4 = ROWS*DM/4;
    const int nw4 = NH*DM*DH/4;
    const int no4 = DM*DM/4;
    cvt_kernel<<<(nx4+255)/256, 256>>>((const float4*)x,  0, nx4);
    cvt_kernel<<<(nw4+255)/256, 256>>>((const float4*)Wq, 1, nw4);
    cvt_kernel<<<(nw4+255)/256, 256>>>((const float4*)Wk, 2, nw4);
    cvt_kernel<<<(nw4+255)/256, 256>>>((const float4*)Wv, 3, nw4);
    cvt_kernel<<<(no4+255)/256, 256>>>((const float4*)Wo, 4, no4);

    qkv_kernel<<<dim3(ROWS/128, 18), 128, GEMM_SMEM>>>(bq, bk, bv);
    flash_kernel<<<dim3(SEQ/QTILE, NH, BATCH), 256, FLASH_SMEM>>>();
    oproj_kernel<<<dim3(ROWS/128, 6), 128, GEMM_SMEM>>>(bo, out);
}

// round 9
// speedup vs baseline: 8.9613x; 1.0726x over previous
#include <cuda_runtime.h>
#include <cuda_fp16.h>
#include <math.h>
#include <stdint.h>

#define BATCH 4
#define SEQ 2048
#define DM 768
#define NH 12
#define DH 64
#define ROWS (BATCH*SEQ)

// fp16 intermediates
__device__ __half g_xh [(size_t)ROWS*DM];
__device__ __half g_wqh[(size_t)NH*DM*DH];   // [h][m][d]
__device__ __half g_wkh[(size_t)NH*DM*DH];
__device__ __half g_wvh[(size_t)NH*DM*DH];
__device__ __half g_woh[(size_t)DM*DM];      // [k][n]
__device__ __half g_q[(size_t)BATCH*NH*SEQ*DH];  // pre-scaled by 0.125*log2e
__device__ __half g_k[(size_t)BATCH*NH*SEQ*DH];
__device__ __half g_v[(size_t)BATCH*NH*SEQ*DH];
__device__ __half g_zh[(size_t)ROWS*DM];

#define QSC 0.1803368801111154f  /* 0.125 * log2(e) */

__device__ __forceinline__ float ex2f(float x) {
    float y; asm("ex2.approx.f32 %0, %1;" : "=f"(y) : "f"(x)); return y;
}
__device__ __forceinline__ void mma16(float* d, const uint32_t* a, const uint32_t* b) {
    asm volatile(
        "mma.sync.aligned.m16n8k16.row.col.f32.f16.f16.f32 "
        "{%0,%1,%2,%3}, {%4,%5,%6,%7}, {%8,%9}, {%0,%1,%2,%3};\n"
        : "+f"(d[0]), "+f"(d[1]), "+f"(d[2]), "+f"(d[3])
        : "r"(a[0]), "r"(a[1]), "r"(a[2]), "r"(a[3]), "r"(b[0]), "r"(b[1]));
}
__device__ __forceinline__ void ldsm4(uint32_t* r, uint32_t addr) {
    asm volatile("ldmatrix.sync.aligned.m8n8.x4.shared.b16 {%0,%1,%2,%3}, [%4];"
        : "=r"(r[0]), "=r"(r[1]), "=r"(r[2]), "=r"(r[3]) : "r"(addr));
}
__device__ __forceinline__ void ldsm4t(uint32_t* r, uint32_t addr) {
    asm volatile("ldmatrix.sync.aligned.m8n8.x4.trans.shared.b16 {%0,%1,%2,%3}, [%4];"
        : "=r"(r[0]), "=r"(r[1]), "=r"(r[2]), "=r"(r[3]) : "r"(addr));
}
__device__ __forceinline__ uint32_t su32(const void* p) {
    return (uint32_t)__cvta_generic_to_shared(p);
}
#define CPA(dst, src) asm volatile("cp.async.cg.shared.global [%0], [%1], 16;" :: "r"(dst), "l"(src))
#define CPC() asm volatile("cp.async.commit_group;")
#define CPW1() asm volatile("cp.async.wait_group 1;")
#define CPW0() asm volatile("cp.async.wait_group 0;")

// ---------------------------------------------------------------------------
// Prep: single fused fp32 -> fp16 conversion over x, Wq, Wk, Wv, Wo.
// ---------------------------------------------------------------------------
#define NX4 (ROWS*DM/4)
#define NW4 (NH*DM*DH/4)
__global__ void __launch_bounds__(256) cvt_all_kernel(
    const float4* __restrict__ x,  const float4* __restrict__ wq,
    const float4* __restrict__ wk, const float4* __restrict__ wv,
    const float4* __restrict__ wo)
{
    int i = blockIdx.x * 256 + threadIdx.x;
    const float4* in;
    __half2* out;
    int j;
    if (i < NX4)                { in = x;  out = (__half2*)g_xh;  j = i; }
    else if (i < NX4 + NW4)     { in = wq; out = (__half2*)g_wqh; j = i - NX4; }
    else if (i < NX4 + 2*NW4)   { in = wk; out = (__half2*)g_wkh; j = i - NX4 - NW4; }
    else if (i < NX4 + 3*NW4)   { in = wv; out = (__half2*)g_wvh; j = i - NX4 - 2*NW4; }
    else if (i < NX4 + 4*NW4)   { in = wo; out = (__half2*)g_woh; j = i - NX4 - 3*NW4; }
    else return;
    float4 v = in[j];
    out[2*j]   = __floats2half2_rn(v.x, v.y);
    out[2*j+1] = __floats2half2_rn(v.z, v.w);
}
#define CVT_TOTAL (NX4 + 4*NW4)

// ===========================================================================
// GEMM: C[128x128] = A[128xK] @ B[Kx128] (fp16 in, fp32 acc). 128 threads,
// 4 warps (64x64 each), BK=64, 2-stage cp.async.
// A smem [128 x 64] pitch 72 halfs; B smem [64 x 128] pitch 136 halfs.
// ===========================================================================
#define APh 72
#define BPh 136
#define A_STh (128*APh)
#define B_STh (64*BPh)
#define GEMM_SMEM ((2*A_STh + 2*B_STh) * 2)

template <typename FB>
__device__ __forceinline__ void gemm128h(const __half* __restrict__ Ag,
                                         FB bsrc, int ntiles,
                                         __half* As, __half* Bs, float acc[4][8][4])
{
    const int tid = threadIdx.x;
    const int lane = tid & 31, wid = tid >> 5;
    const int wm = wid >> 1, wn = wid & 1;
    const int lrow = lane & 15, lch = (lane >> 4) * 8;
    const int j8 = lane >> 3, i8 = lane & 7;

    auto load_tile = [&](int t, int s) {
        #pragma unroll
        for (int i = 0; i < 8; i++) {
            int id = tid + i * 128;
            int r = id >> 3, c8 = id & 7;
            CPA(su32(&As[s*A_STh + r*APh + c8*8]), Ag + (size_t)r * DM + t*64 + c8*8);
        }
        #pragma unroll
        for (int i = 0; i < 8; i++) {
            int id = tid + i * 128;
            int kr = id >> 4, c8 = id & 15;
            CPA(su32(&Bs[s*B_STh + kr*BPh + c8*8]), bsrc(t*64 + kr, c8));
        }
    };

    load_tile(0, 0); CPC();

    for (int t = 0; t < ntiles; t++) {
        if (t + 1 < ntiles) { load_tile(t + 1, (t + 1) & 1); CPC(); CPW1(); }
        else { CPW0(); }
        __syncthreads();

        const __half* A_ = As + (t & 1) * A_STh;
        const __half* B_ = Bs + (t & 1) * B_STh;
        #pragma unroll
        for (int kc = 0; kc < 4; kc++) {
            uint32_t a[4][4], b[8][2];
            #pragma unroll
            for (int mt = 0; mt < 4; mt++)
                ldsm4(a[mt], su32(&A_[(wm*64 + mt*16 + lrow)*APh + kc*16 + lch]));
            #pragma unroll
            for (int ntp = 0; ntp < 4; ntp++) {
                uint32_t r4[4];
                ldsm4t(r4, su32(&B_[(kc*16 + (j8&1)*8 + i8)*BPh + wn*64 + ntp*16 + (j8>>1)*8]));
                b[2*ntp][0]   = r4[0]; b[2*ntp][1]   = r4[1];
                b[2*ntp+1][0] = r4[2]; b[2*ntp+1][1] = r4[3];
            }
            #pragma unroll
            for (int mt = 0; mt < 4; mt++)
                #pragma unroll
                for (int nt = 0; nt < 8; nt++)
                    mma16(acc[mt][nt], a[mt], b[nt]);
        }
        __syncthreads();
    }
}

// ---------------------------------------------------------------------------
// Kernel 1: fused QKV. grid=(ROWS/128, 18), block=128.
// ---------------------------------------------------------------------------
__global__ void __launch_bounds__(128) qkv_kernel(
    const float* __restrict__ bq, const float* __restrict__ bk,
    const float* __restrict__ bv)
{
    extern __shared__ __half smh[];
    __half* As = smh;
    __half* Bs = smh + 2*A_STh;

    const int nb = blockIdx.y;
    const int sel = nb / 6;
    const int h0 = (nb % 6) * 2;
    const __half* W   = (sel == 0) ? g_wqh : ((sel == 1) ? g_wkh : g_wvh);
    const float* bias = (sel == 0) ? bq : ((sel == 1) ? bk : bv);
    __half* out       = (sel == 0) ? g_q : ((sel == 1) ? g_k : g_v);
    const float osc   = (sel == 0) ? QSC : 1.0f;

    const int row0 = blockIdx.x * 128;

    float acc[4][8][4] = {};
    auto bsrc = [&](int k, int c8) {
        return W + ((size_t)(h0 + (c8 >> 3)) * DM + k) * DH + (c8 & 7) * 8;
    };
    gemm128h(g_xh + (size_t)row0 * DM, bsrc, DM/64, As, Bs, acc);

    const int tid = threadIdx.x, lane = tid & 31, wid = tid >> 5;
    const int wm = wid >> 1, wn = wid & 1, lq = lane >> 2, lr = lane & 3;

    #pragma unroll
    for (int mt = 0; mt < 4; mt++) {
        #pragma unroll
        for (int nt = 0; nt < 8; nt++) {
            int c = wn*64 + nt*8 + 2*lr;
            int h = h0 + (c >> 6), d = c & 63;
            float bz0 = bias[h*DH + d], bz1 = bias[h*DH + d + 1];
            #pragma unroll
            for (int half_ = 0; half_ < 2; half_++) {
                int gr = row0 + wm*64 + mt*16 + lq + half_*8;
                int bb = gr / SEQ, s = gr % SEQ;
                size_t base = (((size_t)bb*NH + h)*SEQ + s)*DH + d;
                *(__half2*)(out + base) = __floats2half2_rn(
                    (acc[mt][nt][half_*2+0] + bz0) * osc,
                    (acc[mt][nt][half_*2+1] + bz1) * osc);
            }
        }
    }
}

// ---------------------------------------------------------------------------
// Kernel 3: output projection. grid=(ROWS/128, 6), block=128. fp32 out.
// ---------------------------------------------------------------------------
__global__ void __launch_bounds__(128) oproj_kernel(
    const float* __restrict__ bo, float* __restrict__ out)
{
    extern __shared__ __half smh[];
    __half* As = smh;
    __half* Bs = smh + 2*A_STh;

    const int row0 = blockIdx.x * 128;
    const int n0   = blockIdx.y * 128;

    float acc[4][8][4] = {};
    auto bsrc = [&](int k, int c8) {
        return g_woh + (size_t)k * DM + n0 + c8 * 8;
    };
    gemm128h(g_zh + (size_t)row0 * DM, bsrc, DM/64, As, Bs, acc);

    const int tid = threadIdx.x, lane = tid & 31, wid = tid >> 5;
    const int wm = wid >> 1, wn = wid & 1, lq = lane >> 2, lr = lane & 3;

    #pragma unroll
    for (int mt = 0; mt < 4; mt++) {
        #pragma unroll
        for (int nt = 0; nt < 8; nt++) {
            int c = n0 + wn*64 + nt*8 + 2*lr;
            float bz0 = bo[c], bz1 = bo[c + 1];
            #pragma unroll
            for (int half_ = 0; half_ < 2; half_++) {
                size_t orow = (size_t)(row0 + wm*64 + mt*16 + lq + half_*8) * DM;
                out[orow + c]     = acc[mt][nt][half_*2+0] + bz0;
                out[orow + c + 1] = acc[mt][nt][half_*2+1] + bz1;
            }
        }
    }
}

// ===========================================================================
// Kernel 2: causal flash attention, fp16. grid=(SEQ/256, NH, BATCH), block=256.
// ===========================================================================
#define QTILE 256
#define QPh 72
#define K_STh (64*QPh)
#define Q_OFFh 0
#define P_OFFh (QTILE*QPh)
#define K_OFFh (2*QTILE*QPh)
#define V_OFFh (K_OFFh + 2*K_STh)
#define FLASH_SMEM ((2*QTILE*QPh + 4*K_STh) * 2)

__global__ void __launch_bounds__(256) flash_kernel()
{
    extern __shared__ __half smh[];
    __half* Qs = smh + Q_OFFh;
    __half* Ps = smh + P_OFFh;

    const int qt = (int)gridDim.x - 1 - (int)blockIdx.x;
    const int h  = blockIdx.y;
    const int b  = blockIdx.z;
    const int q0 = qt * QTILE;

    const size_t hb = ((size_t)b * NH + h) * SEQ * DH;
    const __half* qp = g_q + hb;
    const __half* kp = g_k + hb;
    const __half* vp = g_v + hb;

    const int tid  = threadIdx.x;
    const int lane = tid & 31;
    const int wid  = tid >> 5;
    const int lq   = lane >> 2, lr = lane & 3;
    const int lrow = lane & 15, lch = (lane >> 4) * 8;
    const int j8 = lane >> 3, i8 = lane & 7;
    const int wbase = wid * 32;

    auto loadKV = [&](int kt, int s) {
        int k0 = kt * 64;
        #pragma unroll
        for (int i = 0; i < 2; i++) {
            int id = tid + i * 256;
            int r = id >> 3, c8 = id & 7;
            CPA(su32(&smh[K_OFFh + s*K_STh + r*QPh + c8*8]), kp + (size_t)(k0+r)*DH + c8*8);
            CPA(su32(&smh[V_OFFh + s*K_STh + r*QPh + c8*8]), vp + (size_t)(k0+r)*DH + c8*8);
        }
    };

    #pragma unroll
    for (int i = 0; i < 8; i++) {
        int id = tid + i * 256;
        int r = id >> 3, c8 = id & 7;
        CPA(su32(&Qs[r*QPh + c8*8]), qp + (size_t)(q0+r)*DH + c8*8);
    }
    loadKV(0, 0);
    CPC();

    float o[2][8][4] = {};
    float mrow[2][2], lrow2[2][2];
    #pragma unroll
    for (int mt = 0; mt < 2; mt++) { mrow[mt][0]=-INFINITY; mrow[mt][1]=-INFINITY; lrow2[mt][0]=0.f; lrow2[mt][1]=0.f; }

    const int nkt = 4*qt + 4;
    for (int kt = 0; kt < nkt; kt++) {
        if (kt + 1 < nkt) { loadKV(kt + 1, (kt + 1) & 1); CPC(); CPW1(); }
        else { CPW0(); }
        __syncthreads();

        const int k0 = kt * 64;
        const __half* K_ = smh + K_OFFh + (kt & 1) * K_STh;
        const __half* V_ = smh + V_OFFh + (kt & 1) * K_STh;

        // S = Q @ K^T (log2 domain)
        float sf[2][8][4] = {};
        #pragma unroll
        for (int kc = 0; kc < 4; kc++) {
            uint32_t a[2][4], bk2[8][2];
            #pragma unroll
            for (int mt = 0; mt < 2; mt++)
                ldsm4(a[mt], su32(&Qs[(wbase + mt*16 + lrow)*QPh + kc*16 + lch]));
            #pragma unroll
            for (int ntp = 0; ntp < 4; ntp++) {
                uint32_t r4[4];
                ldsm4(r4, su32(&K_[(ntp*16 + (j8>>1)*8 + i8)*QPh + kc*16 + (j8&1)*8]));
                bk2[2*ntp][0]   = r4[0]; bk2[2*ntp][1]   = r4[1];
                bk2[2*ntp+1][0] = r4[2]; bk2[2*ntp+1][1] = r4[3];
            }
            #pragma unroll
            for (int nt = 0; nt < 8; nt++) {
                mma16(sf[0][nt], a[0], bk2[nt]);
                mma16(sf[1][nt], a[1], bk2[nt]);
            }
        }

        // causal mask
        const bool nm = (k0 + 63 > q0 + wbase);
        if (nm) {
            #pragma unroll
            for (int mt = 0; mt < 2; mt++) {
                int grow0 = q0 + wbase + mt*16 + lq;
                #pragma unroll
                for (int nt = 0; nt < 8; nt++) {
                    #pragma unroll
                    for (int e = 0; e < 4; e++) {
                        int gc = k0 + nt*8 + 2*lr + (e & 1);
                        int grow = grow0 + ((e >= 2) ? 8 : 0);
                        if (gc > grow) sf[mt][nt][e] = -1e30f;
                    }
                }
            }
        }

        // online softmax (base-2)
        #pragma unroll
        for (int mt = 0; mt < 2; mt++) {
            float t0 = -INFINITY, t1 = -INFINITY;
            #pragma unroll
            for (int nt = 0; nt < 8; nt++) {
                t0 = fmaxf(t0, fmaxf(sf[mt][nt][0], sf[mt][nt][1]));
                t1 = fmaxf(t1, fmaxf(sf[mt][nt][2], sf[mt][nt][3]));
            }
            t0 = fmaxf(t0, __shfl_xor_sync(0xffffffffu, t0, 1));
            t0 = fmaxf(t0, __shfl_xor_sync(0xffffffffu, t0, 2));
            t1 = fmaxf(t1, __shfl_xor_sync(0xffffffffu, t1, 1));
            t1 = fmaxf(t1, __shfl_xor_sync(0xffffffffu, t1, 2));

            float mn0 = fmaxf(mrow[mt][0], t0), mn1 = fmaxf(mrow[mt][1], t1);
            float sc0 = ex2f(mrow[mt][0] - mn0), sc1 = ex2f(mrow[mt][1] - mn1);
            mrow[mt][0] = mn0; mrow[mt][1] = mn1;

            float s0 = 0.f, s1 = 0.f;
            int rA = wbase + mt*16 + lq;
            #pragma unroll
            for (int nt = 0; nt < 8; nt++) {
                float p0 = ex2f(sf[mt][nt][0] - mn0);
                float p1 = ex2f(sf[mt][nt][1] - mn0);
                float p2 = ex2f(sf[mt][nt][2] - mn1);
                float p3 = ex2f(sf[mt][nt][3] - mn1);
                s0 += p0 + p1; s1 += p2 + p3;
                int col = nt*8 + 2*lr;
                *(__half2*)&Ps[rA*QPh + col]     = __floats2half2_rn(p0, p1);
                *(__half2*)&Ps[(rA+8)*QPh + col] = __floats2half2_rn(p2, p3);
            }
            s0 += __shfl_xor_sync(0xffffffffu, s0, 1);
            s0 += __shfl_xor_sync(0xffffffffu, s0, 2);
            s1 += __shfl_xor_sync(0xffffffffu, s1, 1);
            s1 += __shfl_xor_sync(0xffffffffu, s1, 2);
            lrow2[mt][0] = lrow2[mt][0] * sc0 + s0;
            lrow2[mt][1] = lrow2[mt][1] * sc1 + s1;

            #pragma unroll
            for (int nt = 0; nt < 8; nt++) {
                o[mt][nt][0] *= sc0; o[mt][nt][1] *= sc0;
                o[mt][nt][2] *= sc1; o[mt][nt][3] *= sc1;
            }
        }
        __syncwarp();

        // O += P @ V
        #pragma unroll
        for (int kc = 0; kc < 4; kc++) {
            uint32_t a[2][4], bv2[8][2];
            #pragma unroll
            for (int mt = 0; mt < 2; mt++)
                ldsm4(a[mt], su32(&Ps[(wbase + mt*16 + lrow)*QPh + kc*16 + lch]));
            #pragma unroll
            for (int dp = 0; dp < 4; dp++) {
                uint32_t r4[4];
                ldsm4t(r4, su32(&V_[(kc*16 + (j8&1)*8 + i8)*QPh + dp*16 + (j8>>1)*8]));
                bv2[2*dp][0]   = r4[0]; bv2[2*dp][1]   = r4[1];
                bv2[2*dp+1][0] = r4[2]; bv2[2*dp+1][1] = r4[3];
            }
            #pragma unroll
            for (int nt = 0; nt < 8; nt++) {
                mma16(o[0][nt], a[0], bv2[nt]);
                mma16(o[1][nt], a[1], bv2[nt]);
            }
        }
        __syncthreads();
    }

    #pragma unroll
    for (int mt = 0; mt < 2; mt++) {
        float inv0 = 1.f / lrow2[mt][0], inv1 = 1.f / lrow2[mt][1];
        size_t r0 = (size_t)b * SEQ + q0 + wbase + mt*16 + lq;
        #pragma unroll
        for (int nt = 0; nt < 8; nt++) {
            int col = h*DH + nt*8 + 2*lr;
            *(__half2*)&g_zh[r0 * DM + col] =
                __floats2half2_rn(o[mt][nt][0] * inv0, o[mt][nt][1] * inv0);
            *(__half2*)&g_zh[(r0 + 8) * DM + col] =
                __floats2half2_rn(o[mt][nt][2] * inv1, o[mt][nt][3] * inv1);
        }
    }
}

extern "C" void kernel_launch(void* const* d_in, const int* in_sizes, int n_in,
                              void* d_out, int out_size)
{
    const float* x  = (const float*)d_in[0];
    const float* Wq = (const float*)d_in[1];
    const float* Wk = (const float*)d_in[2];
    const float* Wv = (const float*)d_in[3];
    const float* Wo = (const float*)d_in[4];
    const float* bq = (const float*)d_in[5];
    const float* bk = (const float*)d_in[6];
    const float* bv = (const float*)d_in[7];
    const float* bo = (const float*)d_in[8];
    float* out = (float*)d_out;

    cudaFuncSetAttribute(qkv_kernel,   cudaFuncAttributeMaxDynamicSharedMemorySize, GEMM_SMEM);
    cudaFuncSetAttribute(oproj_kernel, cudaFuncAttributeMaxDynamicSharedMemorySize, GEMM_SMEM);
    cudaFuncSetAttribute(flash_kernel, cudaFuncAttributeMaxDynamicSharedMemorySize, FLASH_SMEM);

    cvt_all_kernel<<<(CVT_TOTAL + 255)/256, 256>>>(
        (const float4*)x, (const float4*)Wq, (const float4*)Wk,
        (const float4*)Wv, (const float4*)Wo);

    qkv_kernel<<<dim3(ROWS/128, 18), 128, GEMM_SMEM>>>(bq, bk, bv);
    flash_kernel<<<dim3(SEQ/QTILE, NH, BATCH), 256, FLASH_SMEM>>>();
    oproj_kernel<<<dim3(ROWS/128, 6), 128, GEMM_SMEM>>>(bo, out);
}

// round 11
// speedup vs baseline: 10.0333x; 1.1196x over previous
#include <cuda_runtime.h>
#include <cuda_fp16.h>
#include <math.h>
#include <stdint.h>
#include <string.h>

#define BATCH 4
#define SEQ 2048
#define DM 768
#define NH 12
#define DH 64
#define ROWS (BATCH*SEQ)

__device__ __half g_xh [(size_t)ROWS*DM];
__device__ __half g_wqh[(size_t)NH*DM*DH];
__device__ __half g_wkh[(size_t)NH*DM*DH];
__device__ __half g_wvh[(size_t)NH*DM*DH];
__device__ __half g_woh[(size_t)DM*DM];
__device__ __half g_q[(size_t)BATCH*NH*SEQ*DH];  // pre-scaled by 0.125*log2e
__device__ __half g_k[(size_t)BATCH*NH*SEQ*DH];
__device__ __half g_v[(size_t)BATCH*NH*SEQ*DH];
__device__ __half g_zh[(size_t)ROWS*DM];

#define QSC 0.1803368801111154f  /* 0.125 * log2(e) */

__device__ __forceinline__ float ex2f(float x) {
    float y; asm("ex2.approx.f32 %0, %1;" : "=f"(y) : "f"(x)); return y;
}
__device__ __forceinline__ uint32_t h2u(__half2 h) {
    uint32_t u;
    memcpy(&u, &h, 4);
    return u;
}
__device__ __forceinline__ void mma16(float* d, const uint32_t* a, const uint32_t* b) {
    asm volatile(
        "mma.sync.aligned.m16n8k16.row.col.f32.f16.f16.f32 "
        "{%0,%1,%2,%3}, {%4,%5,%6,%7}, {%8,%9}, {%0,%1,%2,%3};\n"
        : "+f"(d[0]), "+f"(d[1]), "+f"(d[2]), "+f"(d[3])
        : "r"(a[0]), "r"(a[1]), "r"(a[2]), "r"(a[3]), "r"(b[0]), "r"(b[1]));
}
__device__ __forceinline__ void ldsm4(uint32_t* r, uint32_t addr) {
    asm volatile("ldmatrix.sync.aligned.m8n8.x4.shared.b16 {%0,%1,%2,%3}, [%4];"
        : "=r"(r[0]), "=r"(r[1]), "=r"(r[2]), "=r"(r[3]) : "r"(addr));
}
__device__ __forceinline__ void ldsm4t(uint32_t* r, uint32_t addr) {
    asm volatile("ldmatrix.sync.aligned.m8n8.x4.trans.shared.b16 {%0,%1,%2,%3}, [%4];"
        : "=r"(r[0]), "=r"(r[1]), "=r"(r[2]), "=r"(r[3]) : "r"(addr));
}
__device__ __forceinline__ uint32_t su32(const void* p) {
    return (uint32_t)__cvta_generic_to_shared(p);
}
#define CPA(dst, src) asm volatile("cp.async.cg.shared.global [%0], [%1], 16;" :: "r"(dst), "l"(src))
#define CPC() asm volatile("cp.async.commit_group;")
#define CPW1() asm volatile("cp.async.wait_group 1;")
#define CPW0() asm volatile("cp.async.wait_group 0;")

// ---------------------------------------------------------------------------
// Prep: single fused fp32 -> fp16 conversion
// ---------------------------------------------------------------------------
#define NX4 (ROWS*DM/4)
#define NW4 (NH*DM*DH/4)
__global__ void __launch_bounds__(256) cvt_all_kernel(
    const float4* __restrict__ x,  const float4* __restrict__ wq,
    const float4* __restrict__ wk, const float4* __restrict__ wv,
    const float4* __restrict__ wo)
{
    int i = blockIdx.x * 256 + threadIdx.x;
    const float4* in;
    __half2* out;
    int j;
    if (i < NX4)                { in = x;  out = (__half2*)g_xh;  j = i; }
    else if (i < NX4 + NW4)     { in = wq; out = (__half2*)g_wqh; j = i - NX4; }
    else if (i < NX4 + 2*NW4)   { in = wk; out = (__half2*)g_wkh; j = i - NX4 - NW4; }
    else if (i < NX4 + 3*NW4)   { in = wv; out = (__half2*)g_wvh; j = i - NX4 - 2*NW4; }
    else if (i < NX4 + 4*NW4)   { in = wo; out = (__half2*)g_woh; j = i - NX4 - 3*NW4; }
    else return;
    float4 v = in[j];
    out[2*j]   = __floats2half2_rn(v.x, v.y);
    out[2*j+1] = __floats2half2_rn(v.z, v.w);
}
#define CVT_TOTAL (NX4 + 4*NW4)

// ===========================================================================
// GEMM: C[128x128], 128 threads (4 warps, 64x64), BK=64, 3-stage cp.async,
// single __syncthreads per K-tile.
// ===========================================================================
#define APh 72
#define BPh 136
#define A_STh (128*APh)
#define B_STh (64*BPh)
#define GEMM_SMEM ((3*A_STh + 3*B_STh) * 2)

template <typename FB>
__device__ __forceinline__ void gemm128h(const __half* __restrict__ Ag,
                                         FB bsrc, int ntiles,
                                         __half* As, __half* Bs, float acc[4][8][4])
{
    const int tid = threadIdx.x;
    const int lane = tid & 31, wid = tid >> 5;
    const int wm = wid >> 1, wn = wid & 1;
    const int lrow = lane & 15, lch = (lane >> 4) * 8;
    const int j8 = lane >> 3, i8 = lane & 7;

    auto load_tile = [&](int t, int s) {
        #pragma unroll
        for (int i = 0; i < 8; i++) {
            int id = tid + i * 128;
            int r = id >> 3, c8 = id & 7;
            CPA(su32(&As[s*A_STh + r*APh + c8*8]), Ag + (size_t)r * DM + t*64 + c8*8);
        }
        #pragma unroll
        for (int i = 0; i < 8; i++) {
            int id = tid + i * 128;
            int kr = id >> 4, c8 = id & 15;
            CPA(su32(&Bs[s*B_STh + kr*BPh + c8*8]), bsrc(t*64 + kr, c8));
        }
    };

    load_tile(0, 0); CPC();
    load_tile(1, 1); CPC();

    for (int t = 0; t < ntiles; t++) {
        if (t + 1 < ntiles) { CPW1(); } else { CPW0(); }
        __syncthreads();
        if (t + 2 < ntiles) { load_tile(t + 2, (t + 2) % 3); CPC(); }

        const __half* A_ = As + (t % 3) * A_STh;
        const __half* B_ = Bs + (t % 3) * B_STh;
        #pragma unroll
        for (int kc = 0; kc < 4; kc++) {
            uint32_t a[4][4], b[8][2];
            #pragma unroll
            for (int mt = 0; mt < 4; mt++)
                ldsm4(a[mt], su32(&A_[(wm*64 + mt*16 + lrow)*APh + kc*16 + lch]));
            #pragma unroll
            for (int ntp = 0; ntp < 4; ntp++) {
                uint32_t r4[4];
                ldsm4t(r4, su32(&B_[(kc*16 + (j8&1)*8 + i8)*BPh + wn*64 + ntp*16 + (j8>>1)*8]));
                b[2*ntp][0]   = r4[0]; b[2*ntp][1]   = r4[1];
                b[2*ntp+1][0] = r4[2]; b[2*ntp+1][1] = r4[3];
            }
            #pragma unroll
            for (int mt = 0; mt < 4; mt++)
                #pragma unroll
                for (int nt = 0; nt < 8; nt++)
                    mma16(acc[mt][nt], a[mt], b[nt]);
        }
    }
}

// ---------------------------------------------------------------------------
// Kernel 1: fused QKV. grid=(ROWS/128, 18), block=128.
// ---------------------------------------------------------------------------
__global__ void __launch_bounds__(128) qkv_kernel(
    const float* __restrict__ bq, const float* __restrict__ bk,
    const float* __restrict__ bv)
{
    extern __shared__ __half smh[];
    __half* As = smh;
    __half* Bs = smh + 3*A_STh;

    const int nb = blockIdx.y;
    const int sel = nb / 6;
    const int h0 = (nb % 6) * 2;
    const __half* W   = (sel == 0) ? g_wqh : ((sel == 1) ? g_wkh : g_wvh);
    const float* bias = (sel == 0) ? bq : ((sel == 1) ? bk : bv);
    __half* out       = (sel == 0) ? g_q : ((sel == 1) ? g_k : g_v);
    const float osc   = (sel == 0) ? QSC : 1.0f;

    const int row0 = blockIdx.x * 128;

    float acc[4][8][4] = {};
    auto bsrc = [&](int k, int c8) {
        return W + ((size_t)(h0 + (c8 >> 3)) * DM + k) * DH + (c8 & 7) * 8;
    };
    gemm128h(g_xh + (size_t)row0 * DM, bsrc, DM/64, As, Bs, acc);

    const int tid = threadIdx.x, lane = tid & 31, wid = tid >> 5;
    const int wm = wid >> 1, wn = wid & 1, lq = lane >> 2, lr = lane & 3;

    #pragma unroll
    for (int mt = 0; mt < 4; mt++) {
        #pragma unroll
        for (int nt = 0; nt < 8; nt++) {
            int c = wn*64 + nt*8 + 2*lr;
            int h = h0 + (c >> 6), d = c & 63;
            float bz0 = bias[h*DH + d], bz1 = bias[h*DH + d + 1];
            #pragma unroll
            for (int half_ = 0; half_ < 2; half_++) {
                int gr = row0 + wm*64 + mt*16 + lq + half_*8;
                int bb = gr / SEQ, s = gr % SEQ;
                size_t base = (((size_t)bb*NH + h)*SEQ + s)*DH + d;
                *(__half2*)(out + base) = __floats2half2_rn(
                    (acc[mt][nt][half_*2+0] + bz0) * osc,
                    (acc[mt][nt][half_*2+1] + bz1) * osc);
            }
        }
    }
}

// ---------------------------------------------------------------------------
// Kernel 3: output projection. grid=(ROWS/128, 6), block=128. fp32 out.
// ---------------------------------------------------------------------------
__global__ void __launch_bounds__(128) oproj_kernel(
    const float* __restrict__ bo, float* __restrict__ out)
{
    extern __shared__ __half smh[];
    __half* As = smh;
    __half* Bs = smh + 3*A_STh;

    const int row0 = blockIdx.x * 128;
    const int n0   = blockIdx.y * 128;

    float acc[4][8][4] = {};
    auto bsrc = [&](int k, int c8) {
        return g_woh + (size_t)k * DM + n0 + c8 * 8;
    };
    gemm128h(g_zh + (size_t)row0 * DM, bsrc, DM/64, As, Bs, acc);

    const int tid = threadIdx.x, lane = tid & 31, wid = tid >> 5;
    const int wm = wid >> 1, wn = wid & 1, lq = lane >> 2, lr = lane & 3;

    #pragma unroll
    for (int mt = 0; mt < 4; mt++) {
        #pragma unroll
        for (int nt = 0; nt < 8; nt++) {
            int c = n0 + wn*64 + nt*8 + 2*lr;
            float bz0 = bo[c], bz1 = bo[c + 1];
            #pragma unroll
            for (int half_ = 0; half_ < 2; half_++) {
                size_t orow = (size_t)(row0 + wm*64 + mt*16 + lq + half_*8) * DM;
                out[orow + c]     = acc[mt][nt][half_*2+0] + bz0;
                out[orow + c + 1] = acc[mt][nt][half_*2+1] + bz1;
            }
        }
    }
}

// ===========================================================================
// Kernel 2: causal flash attention, fp16, FA2 register-resident Q and P.
// grid=(SEQ/128, NH, BATCH), block=128 (4 warps x 32 q-rows), k-tile 64,
// 3-stage cp.async K/V, single barrier per tile. No P/Q smem traffic in loop.
// ===========================================================================
#define QTILE 128
#define PHp 72
#define KVST (64*PHp)
#define STG (2*KVST)
#define KV_OFF (QTILE*PHp)
#define FLASH_SMEM ((QTILE*PHp + 3*STG) * 2)

__global__ void __launch_bounds__(128) flash_kernel()
{
    extern __shared__ __half smh[];
    __half* Qs = smh;

    const int qt = (int)gridDim.x - 1 - (int)blockIdx.x;
    const int h  = blockIdx.y;
    const int b  = blockIdx.z;
    const int q0 = qt * QTILE;

    const size_t hb = ((size_t)b * NH + h) * SEQ * DH;
    const __half* qp = g_q + hb;
    const __half* kp = g_k + hb;
    const __half* vp = g_v + hb;

    const int tid  = threadIdx.x;
    const int lane = tid & 31;
    const int wid  = tid >> 5;
    const int lq   = lane >> 2, lr = lane & 3;
    const int lrow = lane & 15, lch = (lane >> 4) * 8;
    const int j8 = lane >> 3, i8 = lane & 7;
    const int wbase = wid * 32;

    auto loadKV = [&](int kt, int s) {
        int k0 = kt * 64;
        #pragma unroll
        for (int i = 0; i < 4; i++) {
            int id = tid + i * 128;
            int r = id >> 3, c8 = id & 7;
            CPA(su32(&smh[KV_OFF + s*STG + r*PHp + c8*8]),        kp + (size_t)(k0+r)*DH + c8*8);
            CPA(su32(&smh[KV_OFF + s*STG + KVST + r*PHp + c8*8]), vp + (size_t)(k0+r)*DH + c8*8);
        }
    };

    // prologue: Q + KV0 (group 0), KV1 (group 1)
    #pragma unroll
    for (int i = 0; i < 8; i++) {
        int id = tid + i * 128;
        int r = id >> 3, c8 = id & 7;
        CPA(su32(&Qs[r*PHp + c8*8]), qp + (size_t)(q0+r)*DH + c8*8);
    }
    loadKV(0, 0);
    CPC();
    const int nkt = 2*qt + 2;
    if (nkt > 1) loadKV(1, 1);
    CPC();

    CPW1();
    __syncthreads();

    // Q fragments into registers (reused across all k-tiles)
    uint32_t qa[2][4][4];
    #pragma unroll
    for (int mt = 0; mt < 2; mt++)
        #pragma unroll
        for (int kc = 0; kc < 4; kc++)
            ldsm4(qa[mt][kc], su32(&Qs[(wbase + mt*16 + lrow)*PHp + kc*16 + lch]));

    float o[2][8][4] = {};
    float mrow[2][2], lrow2[2][2];
    #pragma unroll
    for (int mt = 0; mt < 2; mt++) { mrow[mt][0]=-INFINITY; mrow[mt][1]=-INFINITY; lrow2[mt][0]=0.f; lrow2[mt][1]=0.f; }

    for (int kt = 0; kt < nkt; kt++) {
        if (kt > 0) {
            if (kt + 1 < nkt) { CPW1(); } else { CPW0(); }
            __syncthreads();
        }
        if (kt + 2 < nkt) { loadKV(kt + 2, (kt + 2) % 3); CPC(); }

        const int k0 = kt * 64;
        const __half* K_ = smh + KV_OFF + (kt % 3) * STG;
        const __half* V_ = K_ + KVST;

        // S = Q @ K^T (log2 domain)
        float sf[2][8][4] = {};
        #pragma unroll
        for (int kc = 0; kc < 4; kc++) {
            uint32_t bk2[8][2];
            #pragma unroll
            for (int ntp = 0; ntp < 4; ntp++) {
                uint32_t r4[4];
                ldsm4(r4, su32(&K_[(ntp*16 + (j8>>1)*8 + i8)*PHp + kc*16 + (j8&1)*8]));
                bk2[2*ntp][0]   = r4[0]; bk2[2*ntp][1]   = r4[1];
                bk2[2*ntp+1][0] = r4[2]; bk2[2*ntp+1][1] = r4[3];
            }
            #pragma unroll
            for (int nt = 0; nt < 8; nt++) {
                mma16(sf[0][nt], qa[0][kc], bk2[nt]);
                mma16(sf[1][nt], qa[1][kc], bk2[nt]);
            }
        }

        // causal mask
        const bool nm = (k0 + 63 > q0 + wbase);
        if (nm) {
            #pragma unroll
            for (int mt = 0; mt < 2; mt++) {
                int grow0 = q0 + wbase + mt*16 + lq;
                #pragma unroll
                for (int nt = 0; nt < 8; nt++) {
                    #pragma unroll
                    for (int e = 0; e < 4; e++) {
                        int gc = k0 + nt*8 + 2*lr + (e & 1);
                        int grow = grow0 + ((e >= 2) ? 8 : 0);
                        if (gc > grow) sf[mt][nt][e] = -1e30f;
                    }
                }
            }
        }

        // online softmax (base-2); P packed directly into a-frag registers
        uint32_t plo[2][8], phi[2][8];
        #pragma unroll
        for (int mt = 0; mt < 2; mt++) {
            float t0 = -INFINITY, t1 = -INFINITY;
            #pragma unroll
            for (int nt = 0; nt < 8; nt++) {
                t0 = fmaxf(t0, fmaxf(sf[mt][nt][0], sf[mt][nt][1]));
                t1 = fmaxf(t1, fmaxf(sf[mt][nt][2], sf[mt][nt][3]));
            }
            t0 = fmaxf(t0, __shfl_xor_sync(0xffffffffu, t0, 1));
            t0 = fmaxf(t0, __shfl_xor_sync(0xffffffffu, t0, 2));
            t1 = fmaxf(t1, __shfl_xor_sync(0xffffffffu, t1, 1));
            t1 = fmaxf(t1, __shfl_xor_sync(0xffffffffu, t1, 2));

            float mn0 = fmaxf(mrow[mt][0], t0), mn1 = fmaxf(mrow[mt][1], t1);
            float sc0 = ex2f(mrow[mt][0] - mn0), sc1 = ex2f(mrow[mt][1] - mn1);
            mrow[mt][0] = mn0; mrow[mt][1] = mn1;

            float s0 = 0.f, s1 = 0.f;
            #pragma unroll
            for (int nt = 0; nt < 8; nt++) {
                float p0 = ex2f(sf[mt][nt][0] - mn0);
                float p1 = ex2f(sf[mt][nt][1] - mn0);
                float p2 = ex2f(sf[mt][nt][2] - mn1);
                float p3 = ex2f(sf[mt][nt][3] - mn1);
                s0 += p0 + p1; s1 += p2 + p3;
                plo[mt][nt] = h2u(__floats2half2_rn(p0, p1));
                phi[mt][nt] = h2u(__floats2half2_rn(p2, p3));
            }
            s0 += __shfl_xor_sync(0xffffffffu, s0, 1);
            s0 += __shfl_xor_sync(0xffffffffu, s0, 2);
            s1 += __shfl_xor_sync(0xffffffffu, s1, 1);
            s1 += __shfl_xor_sync(0xffffffffu, s1, 2);
            lrow2[mt][0] = lrow2[mt][0] * sc0 + s0;
            lrow2[mt][1] = lrow2[mt][1] * sc1 + s1;

            #pragma unroll
            for (int nt = 0; nt < 8; nt++) {
                o[mt][nt][0] *= sc0; o[mt][nt][1] *= sc0;
                o[mt][nt][2] *= sc1; o[mt][nt][3] *= sc1;
            }
        }

        // O += P @ V : a-frags straight from plo/phi registers
        #pragma unroll
        for (int kc = 0; kc < 4; kc++) {
            uint32_t bv2[8][2];
            #pragma unroll
            for (int dp = 0; dp < 4; dp++) {
                uint32_t r4[4];
                ldsm4t(r4, su32(&V_[(kc*16 + (j8&1)*8 + i8)*PHp + dp*16 + (j8>>1)*8]));
                bv2[2*dp][0]   = r4[0]; bv2[2*dp][1]   = r4[1];
                bv2[2*dp+1][0] = r4[2]; bv2[2*dp+1][1] = r4[3];
            }
            #pragma unroll
            for (int mt = 0; mt < 2; mt++) {
                uint32_t a[4] = { plo[mt][2*kc], phi[mt][2*kc],
                                  plo[mt][2*kc+1], phi[mt][2*kc+1] };
                #pragma unroll
                for (int nt = 0; nt < 8; nt++)
                    mma16(o[mt][nt], a, bv2[nt]);
            }
        }
    }

    #pragma unroll
    for (int mt = 0; mt < 2; mt++) {
        float inv0 = 1.f / lrow2[mt][0], inv1 = 1.f / lrow2[mt][1];
        size_t r0 = (size_t)b * SEQ + q0 + wbase + mt*16 + lq;
        #pragma unroll
        for (int nt = 0; nt < 8; nt++) {
            int col = h*DH + nt*8 + 2*lr;
            *(__half2*)&g_zh[r0 * DM + col] =
                __floats2half2_rn(o[mt][nt][0] * inv0, o[mt][nt][1] * inv0);
            *(__half2*)&g_zh[(r0 + 8) * DM + col] =
                __floats2half2_rn(o[mt][nt][2] * inv1, o[mt][nt][3] * inv1);
        }
    }
}

extern "C" void kernel_launch(void* const* d_in, const int* in_sizes, int n_in,
                              void* d_out, int out_size)
{
    const float* x  = (const float*)d_in[0];
    const float* Wq = (const float*)d_in[1];
    const float* Wk = (const float*)d_in[2];
    const float* Wv = (const float*)d_in[3];
    const float* Wo = (const float*)d_in[4];
    const float* bq = (const float*)d_in[5];
    const float* bk = (const float*)d_in[6];
    const float* bv = (const float*)d_in[7];
    const float* bo = (const float*)d_in[8];
    float* out = (float*)d_out;

    cudaFuncSetAttribute(qkv_kernel,   cudaFuncAttributeMaxDynamicSharedMemorySize, GEMM_SMEM);
    cudaFuncSetAttribute(oproj_kernel, cudaFuncAttributeMaxDynamicSharedMemorySize, GEMM_SMEM);
    cudaFuncSetAttribute(flash_kernel, cudaFuncAttributeMaxDynamicSharedMemorySize, FLASH_SMEM);

    cvt_all_kernel<<<(CVT_TOTAL + 255)/256, 256>>>(
        (const float4*)x, (const float4*)Wq, (const float4*)Wk,
        (const float4*)Wv, (const float4*)Wo);

    qkv_kernel<<<dim3(ROWS/128, 18), 128, GEMM_SMEM>>>(bq, bk, bv);
    flash_kernel<<<dim3(SEQ/QTILE, NH, BATCH), 128, FLASH_SMEM>>>();
    oproj_kernel<<<dim3(ROWS/128, 6), 128, GEMM_SMEM>>>(bo, out);
}

// round 12
// speedup vs baseline: 10.4100x; 1.0375x over previous
#include <cuda_runtime.h>
#include <cuda_fp16.h>
#include <math.h>
#include <stdint.h>
#include <string.h>

#define BATCH 4
#define SEQ 2048
#define DM 768
#define NH 12
#define DH 64
#define ROWS (BATCH*SEQ)

__device__ __half g_xh [(size_t)ROWS*DM];
__device__ __half g_wqh[(size_t)NH*DM*DH];
__device__ __half g_wkh[(size_t)NH*DM*DH];
__device__ __half g_wvh[(size_t)NH*DM*DH];
__device__ __half g_woh[(size_t)DM*DM];
__device__ __half g_q[(size_t)BATCH*NH*SEQ*DH];  // pre-scaled by 0.125*log2e
__device__ __half g_k[(size_t)BATCH*NH*SEQ*DH];
__device__ __half g_v[(size_t)BATCH*NH*SEQ*DH];
__device__ __half g_zh[(size_t)ROWS*DM];

#define QSC 0.1803368801111154f  /* 0.125 * log2(e) */

__device__ __forceinline__ float ex2f(float x) {
    float y; asm("ex2.approx.f32 %0, %1;" : "=f"(y) : "f"(x)); return y;
}
__device__ __forceinline__ uint32_t h2u(__half2 h) {
    uint32_t u;
    memcpy(&u, &h, 4);
    return u;
}
__device__ __forceinline__ void mma16(float* d, const uint32_t* a, const uint32_t* b) {
    asm volatile(
        "mma.sync.aligned.m16n8k16.row.col.f32.f16.f16.f32 "
        "{%0,%1,%2,%3}, {%4,%5,%6,%7}, {%8,%9}, {%0,%1,%2,%3};\n"
        : "+f"(d[0]), "+f"(d[1]), "+f"(d[2]), "+f"(d[3])
        : "r"(a[0]), "r"(a[1]), "r"(a[2]), "r"(a[3]), "r"(b[0]), "r"(b[1]));
}
__device__ __forceinline__ void ldsm4(uint32_t* r, uint32_t addr) {
    asm volatile("ldmatrix.sync.aligned.m8n8.x4.shared.b16 {%0,%1,%2,%3}, [%4];"
        : "=r"(r[0]), "=r"(r[1]), "=r"(r[2]), "=r"(r[3]) : "r"(addr));
}
__device__ __forceinline__ void ldsm4t(uint32_t* r, uint32_t addr) {
    asm volatile("ldmatrix.sync.aligned.m8n8.x4.trans.shared.b16 {%0,%1,%2,%3}, [%4];"
        : "=r"(r[0]), "=r"(r[1]), "=r"(r[2]), "=r"(r[3]) : "r"(addr));
}
__device__ __forceinline__ uint32_t su32(const void* p) {
    return (uint32_t)__cvta_generic_to_shared(p);
}
#define CPA(dst, src) asm volatile("cp.async.cg.shared.global [%0], [%1], 16;" :: "r"(dst), "l"(src))
#define CPC() asm volatile("cp.async.commit_group;")
#define CPW1() asm volatile("cp.async.wait_group 1;")
#define CPW0() asm volatile("cp.async.wait_group 0;")

// ---------------------------------------------------------------------------
// Prep: single fused fp32 -> fp16 conversion
// ---------------------------------------------------------------------------
#define NX4 (ROWS*DM/4)
#define NW4 (NH*DM*DH/4)
__global__ void __launch_bounds__(256) cvt_all_kernel(
    const float4* __restrict__ x,  const float4* __restrict__ wq,
    const float4* __restrict__ wk, const float4* __restrict__ wv,
    const float4* __restrict__ wo)
{
    int i = blockIdx.x * 256 + threadIdx.x;
    const float4* in;
    __half2* out;
    int j;
    if (i < NX4)                { in = x;  out = (__half2*)g_xh;  j = i; }
    else if (i < NX4 + NW4)     { in = wq; out = (__half2*)g_wqh; j = i - NX4; }
    else if (i < NX4 + 2*NW4)   { in = wk; out = (__half2*)g_wkh; j = i - NX4 - NW4; }
    else if (i < NX4 + 3*NW4)   { in = wv; out = (__half2*)g_wvh; j = i - NX4 - 2*NW4; }
    else if (i < NX4 + 4*NW4)   { in = wo; out = (__half2*)g_woh; j = i - NX4 - 3*NW4; }
    else return;
    float4 v = in[j];
    out[2*j]   = __floats2half2_rn(v.x, v.y);
    out[2*j+1] = __floats2half2_rn(v.z, v.w);
}
#define CVT_TOTAL (NX4 + 4*NW4)

// ===========================================================================
// GEMM: C[128x128], 128 threads (4 warps, 64x64), BK=64, 2-stage cp.async.
// smem 71.7KB -> 3 blocks/SM (12 warps); __launch_bounds__(128,3) caps regs.
// ===========================================================================
#define APh 72
#define BPh 136
#define A_STh (128*APh)
#define B_STh (64*BPh)
#define GEMM_SMEM ((2*A_STh + 2*B_STh) * 2)

template <typename FB>
__device__ __forceinline__ void gemm128h(const __half* __restrict__ Ag,
                                         FB bsrc, int ntiles,
                                         __half* As, __half* Bs, float acc[4][8][4])
{
    const int tid = threadIdx.x;
    const int lane = tid & 31, wid = tid >> 5;
    const int wm = wid >> 1, wn = wid & 1;
    const int lrow = lane & 15, lch = (lane >> 4) * 8;
    const int j8 = lane >> 3, i8 = lane & 7;

    auto load_tile = [&](int t, int s) {
        #pragma unroll
        for (int i = 0; i < 8; i++) {
            int id = tid + i * 128;
            int r = id >> 3, c8 = id & 7;
            CPA(su32(&As[s*A_STh + r*APh + c8*8]), Ag + (size_t)r * DM + t*64 + c8*8);
        }
        #pragma unroll
        for (int i = 0; i < 8; i++) {
            int id = tid + i * 128;
            int kr = id >> 4, c8 = id & 15;
            CPA(su32(&Bs[s*B_STh + kr*BPh + c8*8]), bsrc(t*64 + kr, c8));
        }
    };

    load_tile(0, 0); CPC();

    for (int t = 0; t < ntiles; t++) {
        if (t + 1 < ntiles) { load_tile(t + 1, (t + 1) & 1); CPC(); CPW1(); }
        else { CPW0(); }
        __syncthreads();

        const __half* A_ = As + (t & 1) * A_STh;
        const __half* B_ = Bs + (t & 1) * B_STh;
        #pragma unroll
        for (int kc = 0; kc < 4; kc++) {
            uint32_t a[4][4], b[8][2];
            #pragma unroll
            for (int mt = 0; mt < 4; mt++)
                ldsm4(a[mt], su32(&A_[(wm*64 + mt*16 + lrow)*APh + kc*16 + lch]));
            #pragma unroll
            for (int ntp = 0; ntp < 4; ntp++) {
                uint32_t r4[4];
                ldsm4t(r4, su32(&B_[(kc*16 + (j8&1)*8 + i8)*BPh + wn*64 + ntp*16 + (j8>>1)*8]));
                b[2*ntp][0]   = r4[0]; b[2*ntp][1]   = r4[1];
                b[2*ntp+1][0] = r4[2]; b[2*ntp+1][1] = r4[3];
            }
            #pragma unroll
            for (int mt = 0; mt < 4; mt++)
                #pragma unroll
                for (int nt = 0; nt < 8; nt++)
                    mma16(acc[mt][nt], a[mt], b[nt]);
        }
        __syncthreads();
    }
}

// ---------------------------------------------------------------------------
// Kernel 1: fused QKV. grid=(ROWS/128, 18), block=128.
// ---------------------------------------------------------------------------
__global__ void __launch_bounds__(128, 3) qkv_kernel(
    const float* __restrict__ bq, const float* __restrict__ bk,
    const float* __restrict__ bv)
{
    extern __shared__ __half smh[];
    __half* As = smh;
    __half* Bs = smh + 2*A_STh;

    const int nb = blockIdx.y;
    const int sel = nb / 6;
    const int h0 = (nb % 6) * 2;
    const __half* W   = (sel == 0) ? g_wqh : ((sel == 1) ? g_wkh : g_wvh);
    const float* bias = (sel == 0) ? bq : ((sel == 1) ? bk : bv);
    __half* out       = (sel == 0) ? g_q : ((sel == 1) ? g_k : g_v);
    const float osc   = (sel == 0) ? QSC : 1.0f;

    const int row0 = blockIdx.x * 128;

    float acc[4][8][4] = {};
    auto bsrc = [&](int k, int c8) {
        return W + ((size_t)(h0 + (c8 >> 3)) * DM + k) * DH + (c8 & 7) * 8;
    };
    gemm128h(g_xh + (size_t)row0 * DM, bsrc, DM/64, As, Bs, acc);

    const int tid = threadIdx.x, lane = tid & 31, wid = tid >> 5;
    const int wm = wid >> 1, wn = wid & 1, lq = lane >> 2, lr = lane & 3;

    #pragma unroll
    for (int mt = 0; mt < 4; mt++) {
        #pragma unroll
        for (int nt = 0; nt < 8; nt++) {
            int c = wn*64 + nt*8 + 2*lr;
            int h = h0 + (c >> 6), d = c & 63;
            float bz0 = bias[h*DH + d], bz1 = bias[h*DH + d + 1];
            #pragma unroll
            for (int half_ = 0; half_ < 2; half_++) {
                int gr = row0 + wm*64 + mt*16 + lq + half_*8;
                int bb = gr / SEQ, s = gr % SEQ;
                size_t base = (((size_t)bb*NH + h)*SEQ + s)*DH + d;
                *(__half2*)(out + base) = __floats2half2_rn(
                    (acc[mt][nt][half_*2+0] + bz0) * osc,
                    (acc[mt][nt][half_*2+1] + bz1) * osc);
            }
        }
    }
}

// ---------------------------------------------------------------------------
// Kernel 3: output projection. grid=(ROWS/128, 6), block=128. fp32 out.
// ---------------------------------------------------------------------------
__global__ void __launch_bounds__(128, 3) oproj_kernel(
    const float* __restrict__ bo, float* __restrict__ out)
{
    extern __shared__ __half smh[];
    __half* As = smh;
    __half* Bs = smh + 2*A_STh;

    const int row0 = blockIdx.x * 128;
    const int n0   = blockIdx.y * 128;

    float acc[4][8][4] = {};
    auto bsrc = [&](int k, int c8) {
        return g_woh + (size_t)k * DM + n0 + c8 * 8;
    };
    gemm128h(g_zh + (size_t)row0 * DM, bsrc, DM/64, As, Bs, acc);

    const int tid = threadIdx.x, lane = tid & 31, wid = tid >> 5;
    const int wm = wid >> 1, wn = wid & 1, lq = lane >> 2, lr = lane & 3;

    #pragma unroll
    for (int mt = 0; mt < 4; mt++) {
        #pragma unroll
        for (int nt = 0; nt < 8; nt++) {
            int c = n0 + wn*64 + nt*8 + 2*lr;
            float bz0 = bo[c], bz1 = bo[c + 1];
            #pragma unroll
            for (int half_ = 0; half_ < 2; half_++) {
                size_t orow = (size_t)(row0 + wm*64 + mt*16 + lq + half_*8) * DM;
                out[orow + c]     = acc[mt][nt][half_*2+0] + bz0;
                out[orow + c + 1] = acc[mt][nt][half_*2+1] + bz1;
            }
        }
    }
}

// ===========================================================================
// Kernel 2: causal flash attention, fp16, FA2 register-resident Q and P.
// grid=(SEQ/128, NH, BATCH), block=128 (4 warps x 32 q-rows), k-tile 64,
// 3-stage cp.async K/V, single barrier per tile. (Unchanged from R11.)
// ===========================================================================
#define QTILE 128
#define PHp 72
#define KVST (64*PHp)
#define STG (2*KVST)
#define KV_OFF (QTILE*PHp)
#define FLASH_SMEM ((QTILE*PHp + 3*STG) * 2)

__global__ void __launch_bounds__(128) flash_kernel()
{
    extern __shared__ __half smh[];
    __half* Qs = smh;

    const int qt = (int)gridDim.x - 1 - (int)blockIdx.x;
    const int h  = blockIdx.y;
    const int b  = blockIdx.z;
    const int q0 = qt * QTILE;

    const size_t hb = ((size_t)b * NH + h) * SEQ * DH;
    const __half* qp = g_q + hb;
    const __half* kp = g_k + hb;
    const __half* vp = g_v + hb;

    const int tid  = threadIdx.x;
    const int lane = tid & 31;
    const int wid  = tid >> 5;
    const int lq   = lane >> 2, lr = lane & 3;
    const int lrow = lane & 15, lch = (lane >> 4) * 8;
    const int j8 = lane >> 3, i8 = lane & 7;
    const int wbase = wid * 32;

    auto loadKV = [&](int kt, int s) {
        int k0 = kt * 64;
        #pragma unroll
        for (int i = 0; i < 4; i++) {
            int id = tid + i * 128;
            int r = id >> 3, c8 = id & 7;
            CPA(su32(&smh[KV_OFF + s*STG + r*PHp + c8*8]),        kp + (size_t)(k0+r)*DH + c8*8);
            CPA(su32(&smh[KV_OFF + s*STG + KVST + r*PHp + c8*8]), vp + (size_t)(k0+r)*DH + c8*8);
        }
    };

    #pragma unroll
    for (int i = 0; i < 8; i++) {
        int id = tid + i * 128;
        int r = id >> 3, c8 = id & 7;
        CPA(su32(&Qs[r*PHp + c8*8]), qp + (size_t)(q0+r)*DH + c8*8);
    }
    loadKV(0, 0);
    CPC();
    const int nkt = 2*qt + 2;
    if (nkt > 1) loadKV(1, 1);
    CPC();

    CPW1();
    __syncthreads();

    uint32_t qa[2][4][4];
    #pragma unroll
    for (int mt = 0; mt < 2; mt++)
        #pragma unroll
        for (int kc = 0; kc < 4; kc++)
            ldsm4(qa[mt][kc], su32(&Qs[(wbase + mt*16 + lrow)*PHp + kc*16 + lch]));

    float o[2][8][4] = {};
    float mrow[2][2], lrow2[2][2];
    #pragma unroll
    for (int mt = 0; mt < 2; mt++) { mrow[mt][0]=-INFINITY; mrow[mt][1]=-INFINITY; lrow2[mt][0]=0.f; lrow2[mt][1]=0.f; }

    for (int kt = 0; kt < nkt; kt++) {
        if (kt > 0) {
            if (kt + 1 < nkt) { CPW1(); } else { CPW0(); }
            __syncthreads();
        }
        if (kt + 2 < nkt) { loadKV(kt + 2, (kt + 2) % 3); CPC(); }

        const int k0 = kt * 64;
        const __half* K_ = smh + KV_OFF + (kt % 3) * STG;
        const __half* V_ = K_ + KVST;

        float sf[2][8][4] = {};
        #pragma unroll
        for (int kc = 0; kc < 4; kc++) {
            uint32_t bk2[8][2];
            #pragma unroll
            for (int ntp = 0; ntp < 4; ntp++) {
                uint32_t r4[4];
                ldsm4(r4, su32(&K_[(ntp*16 + (j8>>1)*8 + i8)*PHp + kc*16 + (j8&1)*8]));
                bk2[2*ntp][0]   = r4[0]; bk2[2*ntp][1]   = r4[1];
                bk2[2*ntp+1][0] = r4[2]; bk2[2*ntp+1][1] = r4[3];
            }
            #pragma unroll
            for (int nt = 0; nt < 8; nt++) {
                mma16(sf[0][nt], qa[0][kc], bk2[nt]);
                mma16(sf[1][nt], qa[1][kc], bk2[nt]);
            }
        }

        const bool nm = (k0 + 63 > q0 + wbase);
        if (nm) {
            #pragma unroll
            for (int mt = 0; mt < 2; mt++) {
                int grow0 = q0 + wbase + mt*16 + lq;
                #pragma unroll
                for (int nt = 0; nt < 8; nt++) {
                    #pragma unroll
                    for (int e = 0; e < 4; e++) {
                        int gc = k0 + nt*8 + 2*lr + (e & 1);
                        int grow = grow0 + ((e >= 2) ? 8 : 0);
                        if (gc > grow) sf[mt][nt][e] = -1e30f;
                    }
                }
            }
        }

        uint32_t plo[2][8], phi[2][8];
        #pragma unroll
        for (int mt = 0; mt < 2; mt++) {
            float t0 = -INFINITY, t1 = -INFINITY;
            #pragma unroll
            for (int nt = 0; nt < 8; nt++) {
                t0 = fmaxf(t0, fmaxf(sf[mt][nt][0], sf[mt][nt][1]));
                t1 = fmaxf(t1, fmaxf(sf[mt][nt][2], sf[mt][nt][3]));
            }
            t0 = fmaxf(t0, __shfl_xor_sync(0xffffffffu, t0, 1));
            t0 = fmaxf(t0, __shfl_xor_sync(0xffffffffu, t0, 2));
            t1 = fmaxf(t1, __shfl_xor_sync(0xffffffffu, t1, 1));
            t1 = fmaxf(t1, __shfl_xor_sync(0xffffffffu, t1, 2));

            float mn0 = fmaxf(mrow[mt][0], t0), mn1 = fmaxf(mrow[mt][1], t1);
            float sc0 = ex2f(mrow[mt][0] - mn0), sc1 = ex2f(mrow[mt][1] - mn1);
            mrow[mt][0] = mn0; mrow[mt][1] = mn1;

            float s0 = 0.f, s1 = 0.f;
            #pragma unroll
            for (int nt = 0; nt < 8; nt++) {
                float p0 = ex2f(sf[mt][nt][0] - mn0);
                float p1 = ex2f(sf[mt][nt][1] - mn0);
                float p2 = ex2f(sf[mt][nt][2] - mn1);
                float p3 = ex2f(sf[mt][nt][3] - mn1);
                s0 += p0 + p1; s1 += p2 + p3;
                plo[mt][nt] = h2u(__floats2half2_rn(p0, p1));
                phi[mt][nt] = h2u(__floats2half2_rn(p2, p3));
            }
            s0 += __shfl_xor_sync(0xffffffffu, s0, 1);
            s0 += __shfl_xor_sync(0xffffffffu, s0, 2);
            s1 += __shfl_xor_sync(0xffffffffu, s1, 1);
            s1 += __shfl_xor_sync(0xffffffffu, s1, 2);
            lrow2[mt][0] = lrow2[mt][0] * sc0 + s0;
            lrow2[mt][1] = lrow2[mt][1] * sc1 + s1;

            #pragma unroll
            for (int nt = 0; nt < 8; nt++) {
                o[mt][nt][0] *= sc0; o[mt][nt][1] *= sc0;
                o[mt][nt][2] *= sc1; o[mt][nt][3] *= sc1;
            }
        }

        #pragma unroll
        for (int kc = 0; kc < 4; kc++) {
            uint32_t bv2[8][2];
            #pragma unroll
            for (int dp = 0; dp < 4; dp++) {
                uint32_t r4[4];
                ldsm4t(r4, su32(&V_[(kc*16 + (j8&1)*8 + i8)*PHp + dp*16 + (j8>>1)*8]));
                bv2[2*dp][0]   = r4[0]; bv2[2*dp][1]   = r4[1];
                bv2[2*dp+1][0] = r4[2]; bv2[2*dp+1][1] = r4[3];
            }
            #pragma unroll
            for (int mt = 0; mt < 2; mt++) {
                uint32_t a[4] = { plo[mt][2*kc], phi[mt][2*kc],
                                  plo[mt][2*kc+1], phi[mt][2*kc+1] };
                #pragma unroll
                for (int nt = 0; nt < 8; nt++)
                    mma16(o[mt][nt], a, bv2[nt]);
            }
        }
    }

    #pragma unroll
    for (int mt = 0; mt < 2; mt++) {
        float inv0 = 1.f / lrow2[mt][0], inv1 = 1.f / lrow2[mt][1];
        size_t r0 = (size_t)b * SEQ + q0 + wbase + mt*16 + lq;
        #pragma unroll
        for (int nt = 0; nt < 8; nt++) {
            int col = h*DH + nt*8 + 2*lr;
            *(__half2*)&g_zh[r0 * DM + col] =
                __floats2half2_rn(o[mt][nt][0] * inv0, o[mt][nt][1] * inv0);
            *(__half2*)&g_zh[(r0 + 8) * DM + col] =
                __floats2half2_rn(o[mt][nt][2] * inv1, o[mt][nt][3] * inv1);
        }
    }
}

extern "C" void kernel_launch(void* const* d_in, const int* in_sizes, int n_in,
                              void* d_out, int out_size)
{
    const float* x  = (const float*)d_in[0];
    const float* Wq = (const float*)d_in[1];
    const float* Wk = (const float*)d_in[2];
    const float* Wv = (const float*)d_in[3];
    const float* Wo = (const float*)d_in[4];
    const float* bq = (const float*)d_in[5];
    const float* bk = (const float*)d_in[6];
    const float* bv = (const float*)d_in[7];
    const float* bo = (const float*)d_in[8];
    float* out = (float*)d_out;

    cudaFuncSetAttribute(qkv_kernel,   cudaFuncAttributeMaxDynamicSharedMemorySize, GEMM_SMEM);
    cudaFuncSetAttribute(oproj_kernel, cudaFuncAttributeMaxDynamicSharedMemorySize, GEMM_SMEM);
    cudaFuncSetAttribute(flash_kernel, cudaFuncAttributeMaxDynamicSharedMemorySize, FLASH_SMEM);

    cvt_all_kernel<<<(CVT_TOTAL + 255)/256, 256>>>(
        (const float4*)x, (const float4*)Wq, (const float4*)Wk,
        (const float4*)Wv, (const float4*)Wo);

    qkv_kernel<<<dim3(ROWS/128, 18), 128, GEMM_SMEM>>>(bq, bk, bv);
    flash_kernel<<<dim3(SEQ/QTILE, NH, BATCH), 128, FLASH_SMEM>>>();
    oproj_kernel<<<dim3(ROWS/128, 6), 128, GEMM_SMEM>>>(bo, out);
}

// round 13
// speedup vs baseline: 10.5592x; 1.0143x over previous
#include <cuda_runtime.h>
#include <cuda_fp16.h>
#include <math.h>
#include <stdint.h>
#include <string.h>

#define BATCH 4
#define SEQ 2048
#define DM 768
#define NH 12
#define DH 64
#define ROWS (BATCH*SEQ)

__device__ __half g_xh [(size_t)ROWS*DM];
__device__ __half g_wqh[(size_t)NH*DM*DH];
__device__ __half g_wkh[(size_t)NH*DM*DH];
__device__ __half g_wvh[(size_t)NH*DM*DH];
__device__ __half g_woh[(size_t)DM*DM];
__device__ __half g_q[(size_t)BATCH*NH*SEQ*DH];  // pre-scaled by 0.125*log2e
__device__ __half g_k[(size_t)BATCH*NH*SEQ*DH];
__device__ __half g_v[(size_t)BATCH*NH*SEQ*DH];
__device__ __half g_zh[(size_t)ROWS*DM];

#define QSC 0.1803368801111154f  /* 0.125 * log2(e) */

__device__ __forceinline__ float ex2f(float x) {
    float y; asm("ex2.approx.f32 %0, %1;" : "=f"(y) : "f"(x)); return y;
}
__device__ __forceinline__ uint32_t h2u(__half2 h) {
    uint32_t u;
    memcpy(&u, &h, 4);
    return u;
}
__device__ __forceinline__ void mma16(float* d, const uint32_t* a, const uint32_t* b) {
    asm volatile(
        "mma.sync.aligned.m16n8k16.row.col.f32.f16.f16.f32 "
        "{%0,%1,%2,%3}, {%4,%5,%6,%7}, {%8,%9}, {%0,%1,%2,%3};\n"
        : "+f"(d[0]), "+f"(d[1]), "+f"(d[2]), "+f"(d[3])
        : "r"(a[0]), "r"(a[1]), "r"(a[2]), "r"(a[3]), "r"(b[0]), "r"(b[1]));
}
__device__ __forceinline__ void ldsm4(uint32_t* r, uint32_t addr) {
    asm volatile("ldmatrix.sync.aligned.m8n8.x4.shared.b16 {%0,%1,%2,%3}, [%4];"
        : "=r"(r[0]), "=r"(r[1]), "=r"(r[2]), "=r"(r[3]) : "r"(addr));
}
__device__ __forceinline__ void ldsm4t(uint32_t* r, uint32_t addr) {
    asm volatile("ldmatrix.sync.aligned.m8n8.x4.trans.shared.b16 {%0,%1,%2,%3}, [%4];"
        : "=r"(r[0]), "=r"(r[1]), "=r"(r[2]), "=r"(r[3]) : "r"(addr));
}
__device__ __forceinline__ uint32_t su32(const void* p) {
    return (uint32_t)__cvta_generic_to_shared(p);
}
#define CPA(dst, src) asm volatile("cp.async.cg.shared.global [%0], [%1], 16;" :: "r"(dst), "l"(src))
#define CPC() asm volatile("cp.async.commit_group;")
#define CPW1() asm volatile("cp.async.wait_group 1;")
#define CPW0() asm volatile("cp.async.wait_group 0;")

// ---------------------------------------------------------------------------
// Prep: single fused fp32 -> fp16 conversion
// ---------------------------------------------------------------------------
#define NX4 (ROWS*DM/4)
#define NW4 (NH*DM*DH/4)
__global__ void __launch_bounds__(256) cvt_all_kernel(
    const float4* __restrict__ x,  const float4* __restrict__ wq,
    const float4* __restrict__ wk, const float4* __restrict__ wv,
    const float4* __restrict__ wo)
{
    int i = blockIdx.x * 256 + threadIdx.x;
    const float4* in;
    __half2* out;
    int j;
    if (i < NX4)                { in = x;  out = (__half2*)g_xh;  j = i; }
    else if (i < NX4 + NW4)     { in = wq; out = (__half2*)g_wqh; j = i - NX4; }
    else if (i < NX4 + 2*NW4)   { in = wk; out = (__half2*)g_wkh; j = i - NX4 - NW4; }
    else if (i < NX4 + 3*NW4)   { in = wv; out = (__half2*)g_wvh; j = i - NX4 - 2*NW4; }
    else if (i < NX4 + 4*NW4)   { in = wo; out = (__half2*)g_woh; j = i - NX4 - 3*NW4; }
    else return;
    float4 v = in[j];
    out[2*j]   = __floats2half2_rn(v.x, v.y);
    out[2*j+1] = __floats2half2_rn(v.z, v.w);
}
#define CVT_TOTAL (NX4 + 4*NW4)

// ===========================================================================
// GEMM: C[128x64] = A[128xK] @ B[Kx64], 128 threads (4 warps, 32x64 each),
// BK=64, 2-stage cp.async. smem 55.3KB -> 4 blocks/SM (16 warps/SM).
// A pitch 72 halfs; B pitch 72 halfs.
// ===========================================================================
#define APh 72
#define BPh 72
#define A_STh (128*APh)
#define B_STh (64*BPh)
#define GEMM_SMEM ((2*A_STh + 2*B_STh) * 2)

template <typename FB>
__device__ __forceinline__ void gemm128x64(const __half* __restrict__ Ag,
                                           FB bsrc, int ntiles,
                                           __half* As, __half* Bs, float acc[2][8][4])
{
    const int tid = threadIdx.x;
    const int lane = tid & 31, wid = tid >> 5;
    const int lrow = lane & 15, lch = (lane >> 4) * 8;
    const int j8 = lane >> 3, i8 = lane & 7;

    auto load_tile = [&](int t, int s) {
        #pragma unroll
        for (int i = 0; i < 8; i++) {
            int id = tid + i * 128;
            int r = id >> 3, c8 = id & 7;
            CPA(su32(&As[s*A_STh + r*APh + c8*8]), Ag + (size_t)r * DM + t*64 + c8*8);
        }
        #pragma unroll
        for (int i = 0; i < 4; i++) {
            int id = tid + i * 128;
            int kr = id >> 3, c8 = id & 7;
            CPA(su32(&Bs[s*B_STh + kr*BPh + c8*8]), bsrc(t*64 + kr, c8));
        }
    };

    load_tile(0, 0); CPC();

    for (int t = 0; t < ntiles; t++) {
        if (t + 1 < ntiles) { load_tile(t + 1, (t + 1) & 1); CPC(); CPW1(); }
        else { CPW0(); }
        __syncthreads();

        const __half* A_ = As + (t & 1) * A_STh;
        const __half* B_ = Bs + (t & 1) * B_STh;
        #pragma unroll
        for (int kc = 0; kc < 4; kc++) {
            uint32_t a[2][4], b[8][2];
            #pragma unroll
            for (int mt = 0; mt < 2; mt++)
                ldsm4(a[mt], su32(&A_[(wid*32 + mt*16 + lrow)*APh + kc*16 + lch]));
            #pragma unroll
            for (int ntp = 0; ntp < 4; ntp++) {
                uint32_t r4[4];
                ldsm4t(r4, su32(&B_[(kc*16 + (j8&1)*8 + i8)*BPh + ntp*16 + (j8>>1)*8]));
                b[2*ntp][0]   = r4[0]; b[2*ntp][1]   = r4[1];
                b[2*ntp+1][0] = r4[2]; b[2*ntp+1][1] = r4[3];
            }
            #pragma unroll
            for (int mt = 0; mt < 2; mt++)
                #pragma unroll
                for (int nt = 0; nt < 8; nt++)
                    mma16(acc[mt][nt], a[mt], b[nt]);
        }
        __syncthreads();
    }
}

// ---------------------------------------------------------------------------
// Kernel 1: fused QKV. grid=(ROWS/128, 36), block=128.
// y: sel = y/12, head h = y%12 (N=64 = one head).
// ---------------------------------------------------------------------------
__global__ void __launch_bounds__(128, 4) qkv_kernel(
    const float* __restrict__ bq, const float* __restrict__ bk,
    const float* __restrict__ bv)
{
    extern __shared__ __half smh[];
    __half* As = smh;
    __half* Bs = smh + 2*A_STh;

    const int nb = blockIdx.y;
    const int sel = nb / 12;
    const int h = nb % 12;
    const __half* W   = (sel == 0) ? g_wqh : ((sel == 1) ? g_wkh : g_wvh);
    const float* bias = (sel == 0) ? bq : ((sel == 1) ? bk : bv);
    __half* out       = (sel == 0) ? g_q : ((sel == 1) ? g_k : g_v);
    const float osc   = (sel == 0) ? QSC : 1.0f;

    const int row0 = blockIdx.x * 128;

    float acc[2][8][4] = {};
    auto bsrc = [&](int k, int c8) {
        return W + ((size_t)h * DM + k) * DH + c8 * 8;
    };
    gemm128x64(g_xh + (size_t)row0 * DM, bsrc, DM/64, As, Bs, acc);

    const int tid = threadIdx.x, lane = tid & 31, wid = tid >> 5;
    const int lq = lane >> 2, lr = lane & 3;

    #pragma unroll
    for (int mt = 0; mt < 2; mt++) {
        #pragma unroll
        for (int nt = 0; nt < 8; nt++) {
            int d = nt*8 + 2*lr;
            float bz0 = bias[h*DH + d], bz1 = bias[h*DH + d + 1];
            #pragma unroll
            for (int half_ = 0; half_ < 2; half_++) {
                int gr = row0 + wid*32 + mt*16 + lq + half_*8;
                int bb = gr / SEQ, s = gr % SEQ;
                size_t base = (((size_t)bb*NH + h)*SEQ + s)*DH + d;
                *(__half2*)(out + base) = __floats2half2_rn(
                    (acc[mt][nt][half_*2+0] + bz0) * osc,
                    (acc[mt][nt][half_*2+1] + bz1) * osc);
            }
        }
    }
}

// ---------------------------------------------------------------------------
// Kernel 3: output projection. grid=(ROWS/128, 12), block=128. fp32 out.
// ---------------------------------------------------------------------------
__global__ void __launch_bounds__(128, 4) oproj_kernel(
    const float* __restrict__ bo, float* __restrict__ out)
{
    extern __shared__ __half smh[];
    __half* As = smh;
    __half* Bs = smh + 2*A_STh;

    const int row0 = blockIdx.x * 128;
    const int n0   = blockIdx.y * 64;

    float acc[2][8][4] = {};
    auto bsrc = [&](int k, int c8) {
        return g_woh + (size_t)k * DM + n0 + c8 * 8;
    };
    gemm128x64(g_zh + (size_t)row0 * DM, bsrc, DM/64, As, Bs, acc);

    const int tid = threadIdx.x, lane = tid & 31, wid = tid >> 5;
    const int lq = lane >> 2, lr = lane & 3;

    #pragma unroll
    for (int mt = 0; mt < 2; mt++) {
        #pragma unroll
        for (int nt = 0; nt < 8; nt++) {
            int c = n0 + nt*8 + 2*lr;
            float bz0 = bo[c], bz1 = bo[c + 1];
            #pragma unroll
            for (int half_ = 0; half_ < 2; half_++) {
                size_t orow = (size_t)(row0 + wid*32 + mt*16 + lq + half_*8) * DM;
                out[orow + c]     = acc[mt][nt][half_*2+0] + bz0;
                out[orow + c + 1] = acc[mt][nt][half_*2+1] + bz1;
            }
        }
    }
}

// ===========================================================================
// Kernel 2: causal flash attention, fp16, FA2 register-resident Q and P.
// (Unchanged from R12.)
// ===========================================================================
#define QTILE 128
#define PHp 72
#define KVST (64*PHp)
#define STG (2*KVST)
#define KV_OFF (QTILE*PHp)
#define FLASH_SMEM ((QTILE*PHp + 3*STG) * 2)

__global__ void __launch_bounds__(128) flash_kernel()
{
    extern __shared__ __half smh[];
    __half* Qs = smh;

    const int qt = (int)gridDim.x - 1 - (int)blockIdx.x;
    const int h  = blockIdx.y;
    const int b  = blockIdx.z;
    const int q0 = qt * QTILE;

    const size_t hb = ((size_t)b * NH + h) * SEQ * DH;
    const __half* qp = g_q + hb;
    const __half* kp = g_k + hb;
    const __half* vp = g_v + hb;

    const int tid  = threadIdx.x;
    const int lane = tid & 31;
    const int wid  = tid >> 5;
    const int lq   = lane >> 2, lr = lane & 3;
    const int lrow = lane & 15, lch = (lane >> 4) * 8;
    const int j8 = lane >> 3, i8 = lane & 7;
    const int wbase = wid * 32;

    auto loadKV = [&](int kt, int s) {
        int k0 = kt * 64;
        #pragma unroll
        for (int i = 0; i < 4; i++) {
            int id = tid + i * 128;
            int r = id >> 3, c8 = id & 7;
            CPA(su32(&smh[KV_OFF + s*STG + r*PHp + c8*8]),        kp + (size_t)(k0+r)*DH + c8*8);
            CPA(su32(&smh[KV_OFF + s*STG + KVST + r*PHp + c8*8]), vp + (size_t)(k0+r)*DH + c8*8);
        }
    };

    #pragma unroll
    for (int i = 0; i < 8; i++) {
        int id = tid + i * 128;
        int r = id >> 3, c8 = id & 7;
        CPA(su32(&Qs[r*PHp + c8*8]), qp + (size_t)(q0+r)*DH + c8*8);
    }
    loadKV(0, 0);
    CPC();
    const int nkt = 2*qt + 2;
    if (nkt > 1) loadKV(1, 1);
    CPC();

    CPW1();
    __syncthreads();

    uint32_t qa[2][4][4];
    #pragma unroll
    for (int mt = 0; mt < 2; mt++)
        #pragma unroll
        for (int kc = 0; kc < 4; kc++)
            ldsm4(qa[mt][kc], su32(&Qs[(wbase + mt*16 + lrow)*PHp + kc*16 + lch]));

    float o[2][8][4] = {};
    float mrow[2][2], lrow2[2][2];
    #pragma unroll
    for (int mt = 0; mt < 2; mt++) { mrow[mt][0]=-INFINITY; mrow[mt][1]=-INFINITY; lrow2[mt][0]=0.f; lrow2[mt][1]=0.f; }

    for (int kt = 0; kt < nkt; kt++) {
        if (kt > 0) {
            if (kt + 1 < nkt) { CPW1(); } else { CPW0(); }
            __syncthreads();
        }
        if (kt + 2 < nkt) { loadKV(kt + 2, (kt + 2) % 3); CPC(); }

        const int k0 = kt * 64;
        const __half* K_ = smh + KV_OFF + (kt % 3) * STG;
        const __half* V_ = K_ + KVST;

        float sf[2][8][4] = {};
        #pragma unroll
        for (int kc = 0; kc < 4; kc++) {
            uint32_t bk2[8][2];
            #pragma unroll
            for (int ntp = 0; ntp < 4; ntp++) {
                uint32_t r4[4];
                ldsm4(r4, su32(&K_[(ntp*16 + (j8>>1)*8 + i8)*PHp + kc*16 + (j8&1)*8]));
                bk2[2*ntp][0]   = r4[0]; bk2[2*ntp][1]   = r4[1];
                bk2[2*ntp+1][0] = r4[2]; bk2[2*ntp+1][1] = r4[3];
            }
            #pragma unroll
            for (int nt = 0; nt < 8; nt++) {
                mma16(sf[0][nt], qa[0][kc], bk2[nt]);
                mma16(sf[1][nt], qa[1][kc], bk2[nt]);
            }
        }

        const bool nm = (k0 + 63 > q0 + wbase);
        if (nm) {
            #pragma unroll
            for (int mt = 0; mt < 2; mt++) {
                int grow0 = q0 + wbase + mt*16 + lq;
                #pragma unroll
                for (int nt = 0; nt < 8; nt++) {
                    #pragma unroll
                    for (int e = 0; e < 4; e++) {
                        int gc = k0 + nt*8 + 2*lr + (e & 1);
                        int grow = grow0 + ((e >= 2) ? 8 : 0);
                        if (gc > grow) sf[mt][nt][e] = -1e30f;
                    }
                }
            }
        }

        uint32_t plo[2][8], phi[2][8];
        #pragma unroll
        for (int mt = 0; mt < 2; mt++) {
            float t0 = -INFINITY, t1 = -INFINITY;
            #pragma unroll
            for (int nt = 0; nt < 8; nt++) {
                t0 = fmaxf(t0, fmaxf(sf[mt][nt][0], sf[mt][nt][1]));
                t1 = fmaxf(t1, fmaxf(sf[mt][nt][2], sf[mt][nt][3]));
            }
            t0 = fmaxf(t0, __shfl_xor_sync(0xffffffffu, t0, 1));
            t0 = fmaxf(t0, __shfl_xor_sync(0xffffffffu, t0, 2));
            t1 = fmaxf(t1, __shfl_xor_sync(0xffffffffu, t1, 1));
            t1 = fmaxf(t1, __shfl_xor_sync(0xffffffffu, t1, 2));

            float mn0 = fmaxf(mrow[mt][0], t0), mn1 = fmaxf(mrow[mt][1], t1);
            float sc0 = ex2f(mrow[mt][0] - mn0), sc1 = ex2f(mrow[mt][1] - mn1);
            mrow[mt][0] = mn0; mrow[mt][1] = mn1;

            float s0 = 0.f, s1 = 0.f;
            #pragma unroll
            for (int nt = 0; nt < 8; nt++) {
                float p0 = ex2f(sf[mt][nt][0] - mn0);
                float p1 = ex2f(sf[mt][nt][1] - mn0);
                float p2 = ex2f(sf[mt][nt][2] - mn1);
                float p3 = ex2f(sf[mt][nt][3] - mn1);
                s0 += p0 + p1; s1 += p2 + p3;
                plo[mt][nt] = h2u(__floats2half2_rn(p0, p1));
                phi[mt][nt] = h2u(__floats2half2_rn(p2, p3));
            }
            s0 += __shfl_xor_sync(0xffffffffu, s0, 1);
            s0 += __shfl_xor_sync(0xffffffffu, s0, 2);
            s1 += __shfl_xor_sync(0xffffffffu, s1, 1);
            s1 += __shfl_xor_sync(0xffffffffu, s1, 2);
            lrow2[mt][0] = lrow2[mt][0] * sc0 + s0;
            lrow2[mt][1] = lrow2[mt][1] * sc1 + s1;

            #pragma unroll
            for (int nt = 0; nt < 8; nt++) {
                o[mt][nt][0] *= sc0; o[mt][nt][1] *= sc0;
                o[mt][nt][2] *= sc1; o[mt][nt][3] *= sc1;
            }
        }

        #pragma unroll
        for (int kc = 0; kc < 4; kc++) {
            uint32_t bv2[8][2];
            #pragma unroll
            for (int dp = 0; dp < 4; dp++) {
                uint32_t r4[4];
                ldsm4t(r4, su32(&V_[(kc*16 + (j8&1)*8 + i8)*PHp + dp*16 + (j8>>1)*8]));
                bv2[2*dp][0]   = r4[0]; bv2[2*dp][1]   = r4[1];
                bv2[2*dp+1][0] = r4[2]; bv2[2*dp+1][1] = r4[3];
            }
            #pragma unroll
            for (int mt = 0; mt < 2; mt++) {
                uint32_t a[4] = { plo[mt][2*kc], phi[mt][2*kc],
                                  plo[mt][2*kc+1], phi[mt][2*kc+1] };
                #pragma unroll
                for (int nt = 0; nt < 8; nt++)
                    mma16(o[mt][nt], a, bv2[nt]);
            }
        }
    }

    #pragma unroll
    for (int mt = 0; mt < 2; mt++) {
        float inv0 = 1.f / lrow2[mt][0], inv1 = 1.f / lrow2[mt][1];
        size_t r0 = (size_t)b * SEQ + q0 + wbase + mt*16 + lq;
        #pragma unroll
        for (int nt = 0; nt < 8; nt++) {
            int col = h*DH + nt*8 + 2*lr;
            *(__half2*)&g_zh[r0 * DM + col] =
                __floats2half2_rn(o[mt][nt][0] * inv0, o[mt][nt][1] * inv0);
            *(__half2*)&g_zh[(r0 + 8) * DM + col] =
                __floats2half2_rn(o[mt][nt][2] * inv1, o[mt][nt][3] * inv1);
        }
    }
}

extern "C" void kernel_launch(void* const* d_in, const int* in_sizes, int n_in,
                              void* d_out, int out_size)
{
    const float* x  = (const float*)d_in[0];
    const float* Wq = (const float*)d_in[1];
    const float* Wk = (const float*)d_in[2];
    const float* Wv = (const float*)d_in[3];
    const float* Wo = (const float*)d_in[4];
    const float* bq = (const float*)d_in[5];
    const float* bk = (const float*)d_in[6];
    const float* bv = (const float*)d_in[7];
    const float* bo = (const float*)d_in[8];
    float* out = (float*)d_out;

    cudaFuncSetAttribute(qkv_kernel,   cudaFuncAttributeMaxDynamicSharedMemorySize, GEMM_SMEM);
    cudaFuncSetAttribute(oproj_kernel, cudaFuncAttributeMaxDynamicSharedMemorySize, GEMM_SMEM);
    cudaFuncSetAttribute(flash_kernel, cudaFuncAttributeMaxDynamicSharedMemorySize, FLASH_SMEM);

    cvt_all_kernel<<<(CVT_TOTAL + 255)/256, 256>>>(
        (const float4*)x, (const float4*)Wq, (const float4*)Wk,
        (const float4*)Wv, (const float4*)Wo);

    qkv_kernel<<<dim3(ROWS/128, 36), 128, GEMM_SMEM>>>(bq, bk, bv);
    flash_kernel<<<dim3(SEQ/QTILE, NH, BATCH), 128, FLASH_SMEM>>>();
    oproj_kernel<<<dim3(ROWS/128, 12), 128, GEMM_SMEM>>>(bo, out);
}